// round 2
// baseline (speedup 1.0000x reference)
#include <cuda_runtime.h>
#include <math.h>

#define BV 8
#define SLEN 1024
#define DD 128
#define EE 4
#define ED 512
#define MM (BV*SLEN)          // 8192 rows
#define KGR (SLEN*EE)         // 4096 graph K
#define NSTEPS 5

// ---------------- device scratch (no allocation allowed) ----------------
__device__ float g_Weff[2][ED*DD];        // folded W_in / W_out  [512,128]
__device__ float g_Wrz[256*384];          // stacked [W_r; W_z]
__device__ float g_brz[256];
__device__ float g_gfull[2][MM*ED];       // gi_full / go_full  [8192,512] (16MB each)
__device__ float g_gsum[2][MM*DD];        // gi / go            [8192,128]
__device__ float g_rg[MM*DD];             // r * out
__device__ float g_z[MM*DD];              // z
__device__ float g_stateA[MM*DD];
__device__ float g_stateB[MM*DD];

__device__ __forceinline__ const float* state_ptr(const float* ext, int sel) {
    return sel == 0 ? g_stateA : (sel == 1 ? g_stateB : ext);
}

// ---------------- prep kernels (run once per launch) ----------------
// W_eff[j,d] = sum_e W[j, e*D+d]   (temp is out tiled E times -> fold columns)
__global__ void fold_weights(const float* __restrict__ Win, const float* __restrict__ Wout) {
    int j = blockIdx.x;          // 0..511
    int t = blockIdx.y;          // 0/1
    int d = threadIdx.x;         // 0..127
    const float* W = t ? Wout : Win;
    float s = 0.f;
    #pragma unroll
    for (int e = 0; e < EE; e++) s += W[(size_t)j*ED + e*DD + d];
    g_Weff[t][j*DD + d] = s;
}

__global__ void stack_rz(const float* __restrict__ Wr, const float* __restrict__ Wz,
                         const float* __restrict__ br, const float* __restrict__ bz) {
    int i = blockIdx.x*blockDim.x + threadIdx.x;
    if (i < 256*384) {
        int row = i / 384, col = i % 384;
        g_Wrz[i] = (row < 128) ? Wr[row*384 + col] : Wz[(row-128)*384 + col];
    }
    if (i < 256) g_brz[i] = (i < 128) ? br[i] : bz[i-128];
}

// ---------------- shared A*B^T core: 128x128 tile, Kstep=16, 8x8 microtile ----------------
// A is (up to) 3 concatenated [M,128] segments along K (all lda=128).
// Bt is [N, KTOT] row-major (K-contiguous).
template<int KTOT>
__device__ __forceinline__ void gemm_abT_core(
    const float* __restrict__ A0, const float* __restrict__ A1, const float* __restrict__ A2,
    const float* __restrict__ Bt, int m0, int n0, float (&acc)[8][8])
{
    __shared__ float As[16][128];   // transposed: As[k][m]
    __shared__ float Bs[16][128];   // transposed: Bs[k][n]
    const int tid = threadIdx.x;
    const int tx = tid & 15, ty = tid >> 4;

    for (int k0 = 0; k0 < KTOT; k0 += 16) {
        const float* Aseg = (KTOT == 128) ? A0
                          : (k0 < 128 ? A0 : (k0 < 256 ? A1 : A2));
        const int kl = k0 & 127;
        #pragma unroll
        for (int u0 = 0; u0 < 2; u0++) {
            int u = tid + u0*256;                 // 512 float4 slots
            int row = u >> 2, kq = (u & 3) << 2;
            float4 f = *(const float4*)(Aseg + (size_t)(m0 + row)*DD + kl + kq);
            As[kq+0][row] = f.x; As[kq+1][row] = f.y;
            As[kq+2][row] = f.z; As[kq+3][row] = f.w;
            float4 g = *(const float4*)(Bt + (size_t)(n0 + row)*KTOT + k0 + kq);
            Bs[kq+0][row] = g.x; Bs[kq+1][row] = g.y;
            Bs[kq+2][row] = g.z; Bs[kq+3][row] = g.w;
        }
        __syncthreads();
        #pragma unroll
        for (int kk = 0; kk < 16; kk++) {
            float4 a0 = *(const float4*)&As[kk][ty*8];
            float4 a1 = *(const float4*)&As[kk][ty*8+4];
            float4 b0 = *(const float4*)&Bs[kk][tx*8];
            float4 b1 = *(const float4*)&Bs[kk][tx*8+4];
            float a[8] = {a0.x,a0.y,a0.z,a0.w,a1.x,a1.y,a1.z,a1.w};
            float b[8] = {b0.x,b0.y,b0.z,b0.w,b1.x,b1.y,b1.z,b1.w};
            #pragma unroll
            for (int i = 0; i < 8; i++)
                #pragma unroll
                for (int j = 0; j < 8; j++)
                    acc[i][j] += a[i]*b[j];
        }
        __syncthreads();
    }
}

// ---------------- K1: gi_full/go_full = X @ Weff^T + b  (M=8192, N=512, K=128) ----------------
__global__ __launch_bounds__(256) void k_gfull(
    const float* __restrict__ Xext, int xsel,
    const float* __restrict__ b_in, const float* __restrict__ b_out)
{
    const float* X = state_ptr(Xext, xsel);
    int t = blockIdx.z;
    int m0 = blockIdx.y*128, n0 = blockIdx.x*128;
    float acc[8][8] = {};
    gemm_abT_core<128>(X, X, X, g_Weff[t], m0, n0, acc);
    const float* bias = t ? b_out : b_in;
    float* out = g_gfull[t];
    int tx = threadIdx.x & 15, ty = threadIdx.x >> 4;
    #pragma unroll
    for (int i = 0; i < 8; i++) {
        int m = m0 + ty*8 + i;
        #pragma unroll
        for (int j = 0; j < 8; j++) {
            int n = n0 + tx*8 + j;
            out[(size_t)m*ED + n] = acc[i][j] + bias[n];
        }
    }
}

// ---------------- K2: graph GEMM  C[b] = graph[b] @ gfull[b]  ([1024,4096]@[4096,128]) ----------------
// 64x128 tile, Kstep=16, 4x8 microtile, 256 CTAs for occupancy on 148 SMs.
__global__ __launch_bounds__(256) void k_graph(
    const float* __restrict__ gin, const float* __restrict__ gout)
{
    int z = blockIdx.z;               // 0..15
    int t = z & 1, b = z >> 1;
    const float* A = (t ? gout : gin) + (size_t)b*SLEN*KGR;   // [1024, 4096]
    const float* G = g_gfull[t] + (size_t)b*SLEN*ED;          // [4096, 128]
    float* C = g_gsum[t] + (size_t)b*SLEN*DD;
    int m0 = blockIdx.y * 64;

    __shared__ float As[16][64];     // As[k][m]
    __shared__ float Bs[16][128];    // Bs[k][n] (natural layout of G rows)
    int tid = threadIdx.x;
    int tx = tid & 15, ty = tid >> 4;
    float acc[4][8] = {};

    for (int k0 = 0; k0 < KGR; k0 += 16) {
        {   // A: 64x16 = 256 float4, one per thread, transposed store
            int row = tid >> 2, kq = (tid & 3) << 2;
            float4 f = *(const float4*)(A + (size_t)(m0+row)*KGR + k0 + kq);
            As[kq+0][row]=f.x; As[kq+1][row]=f.y; As[kq+2][row]=f.z; As[kq+3][row]=f.w;
        }
        #pragma unroll
        for (int u0 = 0; u0 < 2; u0++) {   // B: 16x128 = 512 float4, direct
            int u = tid + u0*256;
            int kk = u >> 5, nq = (u & 31) << 2;
            *(float4*)&Bs[kk][nq] = *(const float4*)(G + (size_t)(k0+kk)*DD + nq);
        }
        __syncthreads();
        #pragma unroll
        for (int kk = 0; kk < 16; kk++) {
            float4 av = *(const float4*)&As[kk][ty*4];
            float4 b0 = *(const float4*)&Bs[kk][tx*8];
            float4 b1 = *(const float4*)&Bs[kk][tx*8+4];
            float a[4] = {av.x,av.y,av.z,av.w};
            float bb[8] = {b0.x,b0.y,b0.z,b0.w,b1.x,b1.y,b1.z,b1.w};
            #pragma unroll
            for (int i = 0; i < 4; i++)
                #pragma unroll
                for (int j = 0; j < 8; j++)
                    acc[i][j] += a[i]*bb[j];
        }
        __syncthreads();
    }
    #pragma unroll
    for (int i = 0; i < 4; i++) {
        int m = m0 + ty*4 + i;
        #pragma unroll
        for (int j = 0; j < 8; j++)
            C[(size_t)m*DD + tx*8 + j] = acc[i][j];
    }
}

// ---------------- K3a: r,z = sigmoid([gi,go,X] @ [Wr;Wz]^T + b)  (N=256) ----------------
// stores rg = r*X  and  z
__global__ __launch_bounds__(256) void k_rz(const float* __restrict__ Xext, int xsel)
{
    const float* X = state_ptr(Xext, xsel);
    int m0 = blockIdx.y*128, n0 = blockIdx.x*128;   // n0 in {0,128}
    float acc[8][8] = {};
    gemm_abT_core<384>(g_gsum[0], g_gsum[1], X, g_Wrz, m0, n0, acc);
    int tx = threadIdx.x & 15, ty = threadIdx.x >> 4;
    #pragma unroll
    for (int i = 0; i < 8; i++) {
        int m = m0 + ty*8 + i;
        #pragma unroll
        for (int j = 0; j < 8; j++) {
            int n = n0 + tx*8 + j;
            float s = 1.f/(1.f + expf(-(acc[i][j] + g_brz[n])));
            if (n0 == 0)
                g_rg[(size_t)m*DD + n] = s * X[(size_t)m*DD + n];
            else
                g_z[(size_t)m*DD + (n - 128)] = s;
        }
    }
}

// ---------------- K3b: h = tanh([gi,go,rg] @ Wt^T + bt); out = (1-z)*X + z*h ----------------
__global__ __launch_bounds__(256) void k_update(
    const float* __restrict__ Xext, int xsel,
    const float* __restrict__ Wt, const float* __restrict__ bt,
    float* __restrict__ extOut, int osel)
{
    const float* X = state_ptr(Xext, xsel);
    float* out = (osel == 0) ? g_stateA : (osel == 1 ? g_stateB : extOut);
    int m0 = blockIdx.y*128;
    float acc[8][8] = {};
    gemm_abT_core<384>(g_gsum[0], g_gsum[1], g_rg, Wt, m0, 0, acc);
    int tx = threadIdx.x & 15, ty = threadIdx.x >> 4;
    #pragma unroll
    for (int i = 0; i < 8; i++) {
        int m = m0 + ty*8 + i;
        #pragma unroll
        for (int j = 0; j < 8; j++) {
            int n = tx*8 + j;
            float h = tanhf(acc[i][j] + bt[n]);
            float zv = g_z[(size_t)m*DD + n];
            float xv = X[(size_t)m*DD + n];
            out[(size_t)m*DD + n] = (1.f - zv)*xv + zv*h;
        }
    }
}

// ---------------- launch ----------------
extern "C" void kernel_launch(void* const* d_in, const int* in_sizes, int n_in,
                              void* d_out, int out_size)
{
    const float* input = (const float*)d_in[0];
    const float* gin   = (const float*)d_in[1];
    const float* gout  = (const float*)d_in[2];
    const float* W_in  = (const float*)d_in[3];
    const float* b_in  = (const float*)d_in[4];
    const float* W_out = (const float*)d_in[5];
    const float* b_out = (const float*)d_in[6];
    const float* W_r   = (const float*)d_in[7];
    const float* b_r   = (const float*)d_in[8];
    const float* W_z   = (const float*)d_in[9];
    const float* b_z   = (const float*)d_in[10];
    const float* W_t   = (const float*)d_in[11];
    const float* b_t   = (const float*)d_in[12];

    fold_weights<<<dim3(ED, 2), DD>>>(W_in, W_out);
    stack_rz<<<(256*384 + 255)/256, 256>>>(W_r, W_z, b_r, b_z);

    int xsel = 2;                       // 2 => external pointer (batchinput)
    for (int s = 0; s < NSTEPS; s++) {
        int osel = (s == NSTEPS-1) ? 2 : (s & 1);   // A,B,A,B,d_out
        k_gfull <<<dim3(4, 64, 2), 256>>>(input, xsel, b_in, b_out);
        k_graph <<<dim3(1, 16, 16), 256>>>(gin, gout);
        k_rz    <<<dim3(2, 64), 256>>>(input, xsel);
        k_update<<<dim3(1, 64), 256>>>(input, xsel, W_t, b_t, (float*)d_out, osel);
        xsel = osel;
    }
}

// round 4
// speedup vs baseline: 2.1432x; 2.1432x over previous
#include <cuda_runtime.h>
#include <math.h>
#include <stdint.h>

#define BV 8
#define SLEN 1024
#define DD 128
#define EE 4
#define ED 512
#define MM (BV*SLEN)          // 8192 rows
#define KGR (SLEN*EE)         // 4096 graph K
#define NSTEPS 5
#define KBLK 32               // K per mainloop iter
#define NIT (KGR/KBLK)        // 128
#define APAD 36               // smem row stride in floats (conflict-free frag reads)

// ---------------- device scratch (no allocation allowed) ----------------
__device__ float g_Weff[2][ED*DD];        // folded W_in / W_out  [512,128]
__device__ float g_Wrz[256*384];          // stacked [W_r; W_z]
__device__ float g_brz[256];
__device__ float g_gfullT[(size_t)2*BV*DD*KGR]; // [t][b][d=128][k=4096], tf32-rounded, K-major
__device__ float g_gsum[2][MM*DD];        // gi / go            [8192,128]
__device__ float g_rg[MM*DD];             // r * out
__device__ float g_z[MM*DD];              // z
__device__ float g_stateA[MM*DD];
__device__ float g_stateB[MM*DD];

__device__ __forceinline__ const float* state_ptr(const float* ext, int sel) {
    return sel == 0 ? g_stateA : (sel == 1 ? g_stateB : ext);
}

__device__ __forceinline__ float to_tf32(float x) {
    float y; asm("cvt.rna.tf32.f32 %0, %1;" : "=f"(y) : "f"(x)); return y;
}

// warp-level tf32 MMA: D(16x8) += A(16x8) * B(8x8)
__device__ __forceinline__ void mma_tf32(float* d, const uint32_t* a, const uint32_t* b) {
    asm volatile(
        "mma.sync.aligned.m16n8k8.row.col.f32.tf32.tf32.f32 "
        "{%0,%1,%2,%3}, {%4,%5,%6,%7}, {%8,%9}, {%0,%1,%2,%3};"
        : "+f"(d[0]), "+f"(d[1]), "+f"(d[2]), "+f"(d[3])
        : "r"(a[0]), "r"(a[1]), "r"(a[2]), "r"(a[3]), "r"(b[0]), "r"(b[1]));
}

// ---------------- prep kernels ----------------
__global__ void fold_weights(const float* __restrict__ Win, const float* __restrict__ Wout) {
    int j = blockIdx.x, t = blockIdx.y, d = threadIdx.x;
    const float* W = t ? Wout : Win;
    float s = 0.f;
    #pragma unroll
    for (int e = 0; e < EE; e++) s += W[(size_t)j*ED + e*DD + d];
    g_Weff[t][j*DD + d] = s;
}

__global__ void stack_rz(const float* __restrict__ Wr, const float* __restrict__ Wz,
                         const float* __restrict__ br, const float* __restrict__ bz) {
    int i = blockIdx.x*blockDim.x + threadIdx.x;
    if (i < 256*384) {
        int row = i / 384, col = i % 384;
        g_Wrz[i] = (row < 128) ? Wr[row*384 + col] : Wz[(row-128)*384 + col];
    }
    if (i < 256) g_brz[i] = (i < 128) ? br[i] : bz[i-128];
}

// ---------------- fp32 A*B^T core (k_gfull / k_rz / k_update) ----------------
template<int KTOT>
__device__ __forceinline__ void gemm_abT_core(
    const float* __restrict__ A0, const float* __restrict__ A1, const float* __restrict__ A2,
    const float* __restrict__ Bt, int m0, int n0, float (&acc)[8][8])
{
    __shared__ float As[16][128];
    __shared__ float Bs[16][128];
    const int tid = threadIdx.x;
    const int tx = tid & 15, ty = tid >> 4;

    for (int k0 = 0; k0 < KTOT; k0 += 16) {
        const float* Aseg = (KTOT == 128) ? A0
                          : (k0 < 128 ? A0 : (k0 < 256 ? A1 : A2));
        const int kl = k0 & 127;
        #pragma unroll
        for (int u0 = 0; u0 < 2; u0++) {
            int u = tid + u0*256;
            int row = u >> 2, kq = (u & 3) << 2;
            float4 f = *(const float4*)(Aseg + (size_t)(m0 + row)*DD + kl + kq);
            As[kq+0][row] = f.x; As[kq+1][row] = f.y;
            As[kq+2][row] = f.z; As[kq+3][row] = f.w;
            float4 g = *(const float4*)(Bt + (size_t)(n0 + row)*KTOT + k0 + kq);
            Bs[kq+0][row] = g.x; Bs[kq+1][row] = g.y;
            Bs[kq+2][row] = g.z; Bs[kq+3][row] = g.w;
        }
        __syncthreads();
        #pragma unroll
        for (int kk = 0; kk < 16; kk++) {
            float4 a0 = *(const float4*)&As[kk][ty*8];
            float4 a1 = *(const float4*)&As[kk][ty*8+4];
            float4 b0 = *(const float4*)&Bs[kk][tx*8];
            float4 b1 = *(const float4*)&Bs[kk][tx*8+4];
            float a[8] = {a0.x,a0.y,a0.z,a0.w,a1.x,a1.y,a1.z,a1.w};
            float b[8] = {b0.x,b0.y,b0.z,b0.w,b1.x,b1.y,b1.z,b1.w};
            #pragma unroll
            for (int i = 0; i < 8; i++)
                #pragma unroll
                for (int j = 0; j < 8; j++)
                    acc[i][j] += a[i]*b[j];
        }
        __syncthreads();
    }
}

// ---------------- K1: gfullT = (X @ Weff^T + b), transposed + tf32-rounded ----------------
__global__ __launch_bounds__(256) void k_gfull(
    const float* __restrict__ Xext, int xsel,
    const float* __restrict__ b_in, const float* __restrict__ b_out)
{
    const float* X = state_ptr(Xext, xsel);
    int t = blockIdx.z;
    int m0 = blockIdx.y*128, n0 = blockIdx.x*128;
    float acc[8][8] = {};
    gemm_abT_core<128>(X, X, X, g_Weff[t], m0, n0, acc);
    const float* bias = t ? b_out : b_in;
    int tx = threadIdx.x & 15, ty = threadIdx.x >> 4;
    int bb = m0 >> 10;                 // batch (m-tile never spans batches)
    int e  = n0 >> 7;                  // edge type for this n-tile
    float* outT = g_gfullT + ((size_t)t*BV + bb)*DD*KGR;
    #pragma unroll
    for (int i = 0; i < 8; i++) {
        int m = m0 + ty*8 + i;
        int s = m & (SLEN-1);
        #pragma unroll
        for (int j = 0; j < 8; j++) {
            int n = n0 + tx*8 + j;
            int d = n & 127;
            outT[(size_t)d*KGR + s*4 + e] = to_tf32(acc[i][j] + bias[n]);
        }
    }
}

// ---------------- K2: graph GEMM via warp-level tf32 mma.sync ----------------
// C[b,t][1024,128] = A[1024,4096] @ gfullT[b,t]^T
// 128x128 C tile / CTA, 8 warps of 64x32, K chunked by 32.
__global__ __launch_bounds__(256) void k_graph_wm(
    const float* __restrict__ gin, const float* __restrict__ gout)
{
    __shared__ float As[128*APAD];
    __shared__ float Bs[128*APAD];

    const int tid = threadIdx.x, lane = tid & 31, wid = tid >> 5;
    const int g = lane >> 2, tig = lane & 3;
    const int wm = wid & 1, wn = wid >> 1;      // 2 x 4 warp grid
    const int bt = blockIdx.y, t = bt & 1, b = bt >> 1;
    const int m0 = blockIdx.x * 128;

    const float* A  = (t ? gout : gin) + (size_t)b*SLEN*KGR;
    const float* Bg = g_gfullT + ((size_t)t*BV + b)*DD*KGR;
    float* C = g_gsum[t] + (size_t)b*SLEN*DD;

    // ldg slots: 128 rows x 8 float4 = 1024 slots; 4 per thread
    const int r0 = tid >> 3, q4 = (tid & 7) * 4;     // rows r0, r0+32, r0+64, r0+96

    float acc[4][4][4] = {};
    float4 pa[4], pb[4];

    // prologue: load k-tile 0
    #pragma unroll
    for (int i = 0; i < 4; i++) {
        int r = r0 + i*32;
        pa[i] = *(const float4*)(A  + (size_t)(m0 + r)*KGR + q4);
        pb[i] = *(const float4*)(Bg + (size_t)r*KGR + q4);
        pa[i].x = to_tf32(pa[i].x); pa[i].y = to_tf32(pa[i].y);
        pa[i].z = to_tf32(pa[i].z); pa[i].w = to_tf32(pa[i].w);
    }
    #pragma unroll
    for (int i = 0; i < 4; i++) {
        int r = r0 + i*32;
        *(float4*)&As[r*APAD + q4] = pa[i];
        *(float4*)&Bs[r*APAD + q4] = pb[i];
    }
    __syncthreads();

    #pragma unroll 1
    for (int it = 0; it < NIT; ++it) {
        // prefetch next k-tile into registers (overlaps mma)
        if (it + 1 < NIT) {
            int k0 = (it + 1) * KBLK;
            #pragma unroll
            for (int i = 0; i < 4; i++) {
                int r = r0 + i*32;
                pa[i] = *(const float4*)(A  + (size_t)(m0 + r)*KGR + k0 + q4);
                pb[i] = *(const float4*)(Bg + (size_t)r*KGR + k0 + q4);
                pa[i].x = to_tf32(pa[i].x); pa[i].y = to_tf32(pa[i].y);
                pa[i].z = to_tf32(pa[i].z); pa[i].w = to_tf32(pa[i].w);
            }
        }

        // mma over current smem tile: 4 k-chunks of 8
        #pragma unroll
        for (int kk = 0; kk < 4; kk++) {
            const int kb = kk*8;
            uint32_t afr[4][4], bfr[4][2];
            #pragma unroll
            for (int mf = 0; mf < 4; mf++) {
                int ar = wm*64 + mf*16 + g;
                afr[mf][0] = __float_as_uint(As[ar*APAD      + kb + tig]);
                afr[mf][1] = __float_as_uint(As[(ar+8)*APAD  + kb + tig]);
                afr[mf][2] = __float_as_uint(As[ar*APAD      + kb + tig + 4]);
                afr[mf][3] = __float_as_uint(As[(ar+8)*APAD  + kb + tig + 4]);
            }
            #pragma unroll
            for (int nf = 0; nf < 4; nf++) {
                int br = wn*32 + nf*8 + g;
                bfr[nf][0] = __float_as_uint(Bs[br*APAD + kb + tig]);
                bfr[nf][1] = __float_as_uint(Bs[br*APAD + kb + tig + 4]);
            }
            #pragma unroll
            for (int mf = 0; mf < 4; mf++)
                #pragma unroll
                for (int nf = 0; nf < 4; nf++)
                    mma_tf32(acc[mf][nf], afr[mf], bfr[nf]);
        }
        __syncthreads();

        if (it + 1 < NIT) {
            #pragma unroll
            for (int i = 0; i < 4; i++) {
                int r = r0 + i*32;
                *(float4*)&As[r*APAD + q4] = pa[i];
                *(float4*)&Bs[r*APAD + q4] = pb[i];
            }
            __syncthreads();
        }
    }

    // epilogue: fragment -> C
    #pragma unroll
    for (int mf = 0; mf < 4; mf++) {
        int m = m0 + wm*64 + mf*16 + g;
        #pragma unroll
        for (int nf = 0; nf < 4; nf++) {
            int n = wn*32 + nf*8 + 2*tig;
            float2 v0 = {acc[mf][nf][0], acc[mf][nf][1]};
            float2 v1 = {acc[mf][nf][2], acc[mf][nf][3]};
            *(float2*)(C + (size_t)m*DD + n)     = v0;
            *(float2*)(C + (size_t)(m+8)*DD + n) = v1;
        }
    }
}

// ---------------- K3a: r,z = sigmoid([gi,go,X] @ [Wr;Wz]^T + b) ----------------
__global__ __launch_bounds__(256) void k_rz(const float* __restrict__ Xext, int xsel)
{
    const float* X = state_ptr(Xext, xsel);
    int m0 = blockIdx.y*128, n0 = blockIdx.x*128;
    float acc[8][8] = {};
    gemm_abT_core<384>(g_gsum[0], g_gsum[1], X, g_Wrz, m0, n0, acc);
    int tx = threadIdx.x & 15, ty = threadIdx.x >> 4;
    #pragma unroll
    for (int i = 0; i < 8; i++) {
        int m = m0 + ty*8 + i;
        #pragma unroll
        for (int j = 0; j < 8; j++) {
            int n = n0 + tx*8 + j;
            float s = 1.f/(1.f + expf(-(acc[i][j] + g_brz[n])));
            if (n0 == 0)
                g_rg[(size_t)m*DD + n] = s * X[(size_t)m*DD + n];
            else
                g_z[(size_t)m*DD + (n - 128)] = s;
        }
    }
}

// ---------------- K3b: h = tanh([gi,go,rg] @ Wt^T + bt); out = (1-z)*X + z*h ----------------
__global__ __launch_bounds__(256) void k_update(
    const float* __restrict__ Xext, int xsel,
    const float* __restrict__ Wt, const float* __restrict__ bt,
    float* __restrict__ extOut, int osel)
{
    const float* X = state_ptr(Xext, xsel);
    float* out = (osel == 0) ? g_stateA : (osel == 1 ? g_stateB : extOut);
    int m0 = blockIdx.y*128;
    float acc[8][8] = {};
    gemm_abT_core<384>(g_gsum[0], g_gsum[1], g_rg, Wt, m0, 0, acc);
    int tx = threadIdx.x & 15, ty = threadIdx.x >> 4;
    #pragma unroll
    for (int i = 0; i < 8; i++) {
        int m = m0 + ty*8 + i;
        #pragma unroll
        for (int j = 0; j < 8; j++) {
            int n = tx*8 + j;
            float h = tanhf(acc[i][j] + bt[n]);
            float zv = g_z[(size_t)m*DD + n];
            float xv = X[(size_t)m*DD + n];
            out[(size_t)m*DD + n] = (1.f - zv)*xv + zv*h;
        }
    }
}

// ---------------- launch ----------------
extern "C" void kernel_launch(void* const* d_in, const int* in_sizes, int n_in,
                              void* d_out, int out_size)
{
    const float* input = (const float*)d_in[0];
    const float* gin   = (const float*)d_in[1];
    const float* gout  = (const float*)d_in[2];
    const float* W_in  = (const float*)d_in[3];
    const float* b_in  = (const float*)d_in[4];
    const float* W_out = (const float*)d_in[5];
    const float* b_out = (const float*)d_in[6];
    const float* W_r   = (const float*)d_in[7];
    const float* b_r   = (const float*)d_in[8];
    const float* W_z   = (const float*)d_in[9];
    const float* b_z   = (const float*)d_in[10];
    const float* W_t   = (const float*)d_in[11];
    const float* b_t   = (const float*)d_in[12];

    fold_weights<<<dim3(ED, 2), DD>>>(W_in, W_out);
    stack_rz<<<(256*384 + 255)/256, 256>>>(W_r, W_z, b_r, b_z);

    int xsel = 2;                       // 2 => external pointer (batchinput)
    for (int s = 0; s < NSTEPS; s++) {
        int osel = (s == NSTEPS-1) ? 2 : (s & 1);
        k_gfull   <<<dim3(4, 64, 2), 256>>>(input, xsel, b_in, b_out);
        k_graph_wm<<<dim3(8, 16), 256>>>(gin, gout);
        k_rz      <<<dim3(2, 64), 256>>>(input, xsel);
        k_update  <<<dim3(1, 64), 256>>>(input, xsel, W_t, b_t, (float*)d_out, osel);
        xsel = osel;
    }
}

// round 5
// speedup vs baseline: 3.1780x; 1.4828x over previous
#include <cuda_runtime.h>
#include <math.h>
#include <stdint.h>

#define BV 8
#define SLEN 1024
#define DD 128
#define EE 4
#define ED 512
#define MM (BV*SLEN)          // 8192 rows
#define KGR (SLEN*EE)         // 4096 graph K
#define NSTEPS 5
#define KBLK 32               // K per mainloop iter
#define NIT (KGR/KBLK)        // 128
#define APAD 36               // smem row stride in floats (conflict-free frag reads)

// ---------------- device scratch (no allocation allowed) ----------------
__device__ float g_Weff[2][ED*DD];        // folded W_in / W_out  [512,128], tf32-rounded
__device__ float g_Wrz[256*384];          // stacked [W_r; W_z], tf32-rounded
__device__ float g_WtR[128*384];          // W_t, tf32-rounded
__device__ float g_brz[256];
__device__ float g_gfullT[(size_t)2*BV*DD*KGR]; // [t][b][d=128][k=4096], tf32-rounded, K-major
__device__ float g_gsum[2][MM*DD];        // gi / go            [8192,128]
__device__ float g_rg[MM*DD];             // r * out
__device__ float g_z[MM*DD];              // z
__device__ float g_stateA[MM*DD];
__device__ float g_stateB[MM*DD];

__device__ __forceinline__ const float* state_ptr(const float* ext, int sel) {
    return sel == 0 ? g_stateA : (sel == 1 ? g_stateB : ext);
}

__device__ __forceinline__ float to_tf32(float x) {
    float y; asm("cvt.rna.tf32.f32 %0, %1;" : "=f"(y) : "f"(x)); return y;
}

// warp-level tf32 MMA: D(16x8) += A(16x8) * B(8x8)
__device__ __forceinline__ void mma_tf32(float* d, const uint32_t* a, const uint32_t* b) {
    asm volatile(
        "mma.sync.aligned.m16n8k8.row.col.f32.tf32.tf32.f32 "
        "{%0,%1,%2,%3}, {%4,%5,%6,%7}, {%8,%9}, {%0,%1,%2,%3};"
        : "+f"(d[0]), "+f"(d[1]), "+f"(d[2]), "+f"(d[3])
        : "r"(a[0]), "r"(a[1]), "r"(a[2]), "r"(a[3]), "r"(b[0]), "r"(b[1]));
}

// ---------------- prep kernels ----------------
__global__ void fold_weights(const float* __restrict__ Win, const float* __restrict__ Wout) {
    int j = blockIdx.x, t = blockIdx.y, d = threadIdx.x;
    const float* W = t ? Wout : Win;
    float s = 0.f;
    #pragma unroll
    for (int e = 0; e < EE; e++) s += W[(size_t)j*ED + e*DD + d];
    g_Weff[t][j*DD + d] = to_tf32(s);
}

__global__ void stack_rz(const float* __restrict__ Wr, const float* __restrict__ Wz,
                         const float* __restrict__ br, const float* __restrict__ bz,
                         const float* __restrict__ Wt) {
    int i = blockIdx.x*blockDim.x + threadIdx.x;
    if (i < 256*384) {
        int row = i / 384, col = i % 384;
        g_Wrz[i] = to_tf32((row < 128) ? Wr[row*384 + col] : Wz[(row-128)*384 + col]);
    }
    if (i < 128*384) g_WtR[i] = to_tf32(Wt[i]);
    if (i < 256) g_brz[i] = (i < 128) ? br[i] : bz[i-128];
}

// ---------------- warp-MMA core: 128x128 C tile, A = up to 3 [M,128] segments ----------------
// Bt is [N, KTOT] row-major (K-contiguous = col-major B fragment layout), pre-tf32-rounded.
template<int KTOT>
__device__ __forceinline__ void wm_core(
    const float* __restrict__ A0, const float* __restrict__ A1, const float* __restrict__ A2,
    const float* __restrict__ Bt, int m0, int n0, float (&acc)[4][4][4])
{
    __shared__ float As[128*APAD];
    __shared__ float Bs[128*APAD];
    const int tid = threadIdx.x, lane = tid & 31, wid = tid >> 5;
    const int g = lane >> 2, tig = lane & 3;
    const int wm = wid & 1, wn = wid >> 1;
    const int r0 = tid >> 3, q4 = (tid & 7) * 4;
    constexpr int NITL = KTOT / KBLK;
    float4 pa[4], pb[4];

    // load k-tile `it` into registers
    auto ldtile = [&](int it) {
        int k0 = it * KBLK;
        const float* Aseg = (KTOT == 128) ? A0 : (k0 < 128 ? A0 : (k0 < 256 ? A1 : A2));
        int kl = k0 & 127;
        #pragma unroll
        for (int i = 0; i < 4; i++) {
            int r = r0 + i*32;
            pa[i] = *(const float4*)(Aseg + (size_t)(m0 + r)*DD + kl + q4);
            pb[i] = *(const float4*)(Bt + (size_t)(n0 + r)*KTOT + k0 + q4);
            pa[i].x = to_tf32(pa[i].x); pa[i].y = to_tf32(pa[i].y);
            pa[i].z = to_tf32(pa[i].z); pa[i].w = to_tf32(pa[i].w);
        }
    };
    auto sttile = [&]() {
        #pragma unroll
        for (int i = 0; i < 4; i++) {
            int r = r0 + i*32;
            *(float4*)&As[r*APAD + q4] = pa[i];
            *(float4*)&Bs[r*APAD + q4] = pb[i];
        }
    };

    ldtile(0); sttile();
    __syncthreads();

    #pragma unroll 1
    for (int it = 0; it < NITL; ++it) {
        if (it + 1 < NITL) ldtile(it + 1);
        #pragma unroll
        for (int kk = 0; kk < 4; kk++) {
            const int kb = kk*8;
            uint32_t afr[4][4], bfr[4][2];
            #pragma unroll
            for (int mf = 0; mf < 4; mf++) {
                int ar = wm*64 + mf*16 + g;
                afr[mf][0] = __float_as_uint(As[ar*APAD     + kb + tig]);
                afr[mf][1] = __float_as_uint(As[(ar+8)*APAD + kb + tig]);
                afr[mf][2] = __float_as_uint(As[ar*APAD     + kb + tig + 4]);
                afr[mf][3] = __float_as_uint(As[(ar+8)*APAD + kb + tig + 4]);
            }
            #pragma unroll
            for (int nf = 0; nf < 4; nf++) {
                int br = wn*32 + nf*8 + g;
                bfr[nf][0] = __float_as_uint(Bs[br*APAD + kb + tig]);
                bfr[nf][1] = __float_as_uint(Bs[br*APAD + kb + tig + 4]);
            }
            #pragma unroll
            for (int mf = 0; mf < 4; mf++)
                #pragma unroll
                for (int nf = 0; nf < 4; nf++)
                    mma_tf32(acc[mf][nf], afr[mf], bfr[nf]);
        }
        __syncthreads();
        if (it + 1 < NITL) { sttile(); __syncthreads(); }
    }
}

// per-thread fragment coordinates (within 128x128 tile)
#define FRAG_SETUP() \
    const int lane = threadIdx.x & 31, wid = threadIdx.x >> 5; \
    const int g = lane >> 2, tig = lane & 3; \
    const int wm = wid & 1, wn = wid >> 1;

// ---------------- K1: gfullT = (X @ Weff^T + b), transposed + tf32-rounded ----------------
__global__ __launch_bounds__(256) void k_gfull_mma(
    const float* __restrict__ Xext, int xsel,
    const float* __restrict__ b_in, const float* __restrict__ b_out)
{
    const float* X = state_ptr(Xext, xsel);
    const int t = blockIdx.z;
    const int m0 = blockIdx.y*128, n0 = blockIdx.x*128;
    float acc[4][4][4] = {};
    wm_core<128>(X, X, X, g_Weff[t], m0, n0, acc);

    const float* bias = t ? b_out : b_in;
    FRAG_SETUP();
    const int bb = m0 >> 10, e = n0 >> 7;
    float* outT = g_gfullT + ((size_t)t*BV + bb)*DD*KGR;
    #pragma unroll
    for (int mf = 0; mf < 4; mf++) {
        int m = m0 + wm*64 + mf*16 + g;
        int s0 = m & (SLEN-1), s1 = (m+8) & (SLEN-1);
        #pragma unroll
        for (int nf = 0; nf < 4; nf++) {
            int n = n0 + wn*32 + nf*8 + 2*tig;
            int d0 = n & 127, d1 = (n+1) & 127;
            outT[(size_t)d0*KGR + s0*4 + e] = to_tf32(acc[mf][nf][0] + bias[n]);
            outT[(size_t)d1*KGR + s0*4 + e] = to_tf32(acc[mf][nf][1] + bias[n+1]);
            outT[(size_t)d0*KGR + s1*4 + e] = to_tf32(acc[mf][nf][2] + bias[n]);
            outT[(size_t)d1*KGR + s1*4 + e] = to_tf32(acc[mf][nf][3] + bias[n+1]);
        }
    }
}

// ---------------- K2: graph GEMM via warp-level tf32 mma.sync (unchanged from R4) ----------------
__global__ __launch_bounds__(256) void k_graph_wm(
    const float* __restrict__ gin, const float* __restrict__ gout)
{
    __shared__ float As[128*APAD];
    __shared__ float Bs[128*APAD];

    const int tid = threadIdx.x, lane = tid & 31, wid = tid >> 5;
    const int g = lane >> 2, tig = lane & 3;
    const int wm = wid & 1, wn = wid >> 1;
    const int bt = blockIdx.y, t = bt & 1, b = bt >> 1;
    const int m0 = blockIdx.x * 128;

    const float* A  = (t ? gout : gin) + (size_t)b*SLEN*KGR;
    const float* Bg = g_gfullT + ((size_t)t*BV + b)*DD*KGR;
    float* C = g_gsum[t] + (size_t)b*SLEN*DD;

    const int r0 = tid >> 3, q4 = (tid & 7) * 4;

    float acc[4][4][4] = {};
    float4 pa[4], pb[4];

    #pragma unroll
    for (int i = 0; i < 4; i++) {
        int r = r0 + i*32;
        pa[i] = *(const float4*)(A  + (size_t)(m0 + r)*KGR + q4);
        pb[i] = *(const float4*)(Bg + (size_t)r*KGR + q4);
        pa[i].x = to_tf32(pa[i].x); pa[i].y = to_tf32(pa[i].y);
        pa[i].z = to_tf32(pa[i].z); pa[i].w = to_tf32(pa[i].w);
    }
    #pragma unroll
    for (int i = 0; i < 4; i++) {
        int r = r0 + i*32;
        *(float4*)&As[r*APAD + q4] = pa[i];
        *(float4*)&Bs[r*APAD + q4] = pb[i];
    }
    __syncthreads();

    #pragma unroll 1
    for (int it = 0; it < NIT; ++it) {
        if (it + 1 < NIT) {
            int k0 = (it + 1) * KBLK;
            #pragma unroll
            for (int i = 0; i < 4; i++) {
                int r = r0 + i*32;
                pa[i] = *(const float4*)(A  + (size_t)(m0 + r)*KGR + k0 + q4);
                pb[i] = *(const float4*)(Bg + (size_t)r*KGR + k0 + q4);
                pa[i].x = to_tf32(pa[i].x); pa[i].y = to_tf32(pa[i].y);
                pa[i].z = to_tf32(pa[i].z); pa[i].w = to_tf32(pa[i].w);
            }
        }
        #pragma unroll
        for (int kk = 0; kk < 4; kk++) {
            const int kb = kk*8;
            uint32_t afr[4][4], bfr[4][2];
            #pragma unroll
            for (int mf = 0; mf < 4; mf++) {
                int ar = wm*64 + mf*16 + g;
                afr[mf][0] = __float_as_uint(As[ar*APAD     + kb + tig]);
                afr[mf][1] = __float_as_uint(As[(ar+8)*APAD + kb + tig]);
                afr[mf][2] = __float_as_uint(As[ar*APAD     + kb + tig + 4]);
                afr[mf][3] = __float_as_uint(As[(ar+8)*APAD + kb + tig + 4]);
            }
            #pragma unroll
            for (int nf = 0; nf < 4; nf++) {
                int br = wn*32 + nf*8 + g;
                bfr[nf][0] = __float_as_uint(Bs[br*APAD + kb + tig]);
                bfr[nf][1] = __float_as_uint(Bs[br*APAD + kb + tig + 4]);
            }
            #pragma unroll
            for (int mf = 0; mf < 4; mf++)
                #pragma unroll
                for (int nf = 0; nf < 4; nf++)
                    mma_tf32(acc[mf][nf], afr[mf], bfr[nf]);
        }
        __syncthreads();
        if (it + 1 < NIT) {
            #pragma unroll
            for (int i = 0; i < 4; i++) {
                int r = r0 + i*32;
                *(float4*)&As[r*APAD + q4] = pa[i];
                *(float4*)&Bs[r*APAD + q4] = pb[i];
            }
            __syncthreads();
        }
    }

    #pragma unroll
    for (int mf = 0; mf < 4; mf++) {
        int m = m0 + wm*64 + mf*16 + g;
        #pragma unroll
        for (int nf = 0; nf < 4; nf++) {
            int n = wn*32 + nf*8 + 2*tig;
            float2 v0 = {acc[mf][nf][0], acc[mf][nf][1]};
            float2 v1 = {acc[mf][nf][2], acc[mf][nf][3]};
            *(float2*)(C + (size_t)m*DD + n)     = v0;
            *(float2*)(C + (size_t)(m+8)*DD + n) = v1;
        }
    }
}

// ---------------- K3a: r,z = sigmoid([gi,go,X] @ [Wr;Wz]^T + b); rg = r*X ----------------
__global__ __launch_bounds__(256) void k_rz_mma(const float* __restrict__ Xext, int xsel)
{
    const float* X = state_ptr(Xext, xsel);
    const int m0 = blockIdx.y*128, n0 = blockIdx.x*128;   // n0 in {0,128}
    float acc[4][4][4] = {};
    wm_core<384>(g_gsum[0], g_gsum[1], X, g_Wrz, m0, n0, acc);

    FRAG_SETUP();
    #pragma unroll
    for (int mf = 0; mf < 4; mf++) {
        int m = m0 + wm*64 + mf*16 + g;
        #pragma unroll
        for (int nf = 0; nf < 4; nf++) {
            int n = n0 + wn*32 + nf*8 + 2*tig;
            #pragma unroll
            for (int v = 0; v < 4; v++) {
                int mm = (v < 2) ? m : m + 8;
                int nn = n + (v & 1);
                float s = 1.f/(1.f + expf(-(acc[mf][nf][v] + g_brz[nn])));
                if (n0 == 0)
                    g_rg[(size_t)mm*DD + nn] = s * X[(size_t)mm*DD + nn];
                else
                    g_z[(size_t)mm*DD + (nn - 128)] = s;
            }
        }
    }
}

// ---------------- K3b: h = tanh([gi,go,rg] @ Wt^T + bt); out = (1-z)*X + z*h ----------------
__global__ __launch_bounds__(256) void k_update_mma(
    const float* __restrict__ Xext, int xsel,
    const float* __restrict__ bt,
    float* __restrict__ extOut, int osel)
{
    const float* X = state_ptr(Xext, xsel);
    float* out = (osel == 0) ? g_stateA : (osel == 1 ? g_stateB : extOut);
    const int m0 = blockIdx.y*128;
    float acc[4][4][4] = {};
    wm_core<384>(g_gsum[0], g_gsum[1], g_rg, g_WtR, m0, 0, acc);

    FRAG_SETUP();
    #pragma unroll
    for (int mf = 0; mf < 4; mf++) {
        int m = m0 + wm*64 + mf*16 + g;
        #pragma unroll
        for (int nf = 0; nf < 4; nf++) {
            int n = wn*32 + nf*8 + 2*tig;
            #pragma unroll
            for (int v = 0; v < 4; v++) {
                int mm = (v < 2) ? m : m + 8;
                int nn = n + (v & 1);
                float h = tanhf(acc[mf][nf][v] + bt[nn]);
                float zv = g_z[(size_t)mm*DD + nn];
                float xv = X[(size_t)mm*DD + nn];
                out[(size_t)mm*DD + nn] = (1.f - zv)*xv + zv*h;
            }
        }
    }
}

// ---------------- launch ----------------
extern "C" void kernel_launch(void* const* d_in, const int* in_sizes, int n_in,
                              void* d_out, int out_size)
{
    const float* input = (const float*)d_in[0];
    const float* gin   = (const float*)d_in[1];
    const float* gout  = (const float*)d_in[2];
    const float* W_in  = (const float*)d_in[3];
    const float* b_in  = (const float*)d_in[4];
    const float* W_out = (const float*)d_in[5];
    const float* b_out = (const float*)d_in[6];
    const float* W_r   = (const float*)d_in[7];
    const float* b_r   = (const float*)d_in[8];
    const float* W_z   = (const float*)d_in[9];
    const float* b_z   = (const float*)d_in[10];
    const float* W_t   = (const float*)d_in[11];
    const float* b_t   = (const float*)d_in[12];

    fold_weights<<<dim3(ED, 2), DD>>>(W_in, W_out);
    stack_rz<<<(256*384 + 255)/256, 256>>>(W_r, W_z, b_r, b_z, W_t);

    int xsel = 2;                       // 2 => external pointer (batchinput)
    for (int s = 0; s < NSTEPS; s++) {
        int osel = (s == NSTEPS-1) ? 2 : (s & 1);
        k_gfull_mma <<<dim3(4, 64, 2), 256>>>(input, xsel, b_in, b_out);
        k_graph_wm  <<<dim3(8, 16), 256>>>(gin, gout);
        k_rz_mma    <<<dim3(2, 64), 256>>>(input, xsel);
        k_update_mma<<<dim3(1, 64), 256>>>(input, xsel, b_t, (float*)d_out, osel);
        xsel = osel;
    }
}

// round 6
// speedup vs baseline: 5.8134x; 1.8292x over previous
#include <cuda_runtime.h>
#include <cuda_bf16.h>
#include <math.h>
#include <stdint.h>

#define BV 8
#define SLEN 1024
#define DD 128
#define EE 4
#define ED 512
#define MM (BV*SLEN)          // 8192 rows
#define KGR (SLEN*EE)         // 4096 graph K
#define NSTEPS 5
#define KBLK 32               // K per mainloop iter (tf32 gate kernels)
#define APAD 36               // smem row stride floats (gate kernels)

// graph bf16 kernel params
#define GSTG 4                // cp.async stages
#define KB2 64                // bf16 K per stage (128B rows)
#define NIT2 (KGR/KB2)        // 64
#define ROWB 72               // bf16 elems per smem row (144B stride -> conflict-free)
#define TILE_BYTES (128*ROWB*2)   // 18432 B per operand tile
#define STG_BYTES (2*TILE_BYTES)  // A+B per stage
#define GSMEM (GSTG*STG_BYTES)    // 147456 B

// ---------------- device scratch (no allocation allowed) ----------------
__device__ float g_Weff[2][ED*DD];        // folded W_in/W_out [512,128], tf32
__device__ float g_Wrz[256*384];          // stacked [W_r; W_z], tf32
__device__ float g_WtR[128*384];          // W_t, tf32
__device__ float g_brz[256];
__device__ __nv_bfloat16 g_gbf[(size_t)2*MM*KGR];      // bf16 copies of gin/gout (134MB)
__device__ __nv_bfloat16 g_gfullT[(size_t)2*BV*DD*KGR]; // [t][b][d=128][k=4096] bf16 K-major
__device__ float g_gsum[2][MM*DD];        // gi / go  [8192,128]
__device__ float g_rg[MM*DD];             // r * out
__device__ float g_z[MM*DD];              // z
__device__ float g_stateA[MM*DD];
__device__ float g_stateB[MM*DD];

__device__ __forceinline__ const float* state_ptr(const float* ext, int sel) {
    return sel == 0 ? g_stateA : (sel == 1 ? g_stateB : ext);
}
__device__ __forceinline__ float to_tf32(float x) {
    float y; asm("cvt.rna.tf32.f32 %0, %1;" : "=f"(y) : "f"(x)); return y;
}
// tf32 warp MMA (gate kernels)
__device__ __forceinline__ void mma_tf32(float* d, const uint32_t* a, const uint32_t* b) {
    asm volatile(
        "mma.sync.aligned.m16n8k8.row.col.f32.tf32.tf32.f32 "
        "{%0,%1,%2,%3}, {%4,%5,%6,%7}, {%8,%9}, {%0,%1,%2,%3};"
        : "+f"(d[0]), "+f"(d[1]), "+f"(d[2]), "+f"(d[3])
        : "r"(a[0]), "r"(a[1]), "r"(a[2]), "r"(a[3]), "r"(b[0]), "r"(b[1]));
}
// bf16 warp MMA (graph kernel)
__device__ __forceinline__ void mma_bf16(float* d, const uint32_t* a, const uint32_t* b) {
    asm volatile(
        "mma.sync.aligned.m16n8k16.row.col.f32.bf16.bf16.f32 "
        "{%0,%1,%2,%3}, {%4,%5,%6,%7}, {%8,%9}, {%0,%1,%2,%3};"
        : "+f"(d[0]), "+f"(d[1]), "+f"(d[2]), "+f"(d[3])
        : "r"(a[0]), "r"(a[1]), "r"(a[2]), "r"(a[3]), "r"(b[0]), "r"(b[1]));
}
__device__ __forceinline__ void ldm_x4(uint32_t* r, uint32_t addr) {
    asm volatile("ldmatrix.sync.aligned.m8n8.x4.shared.b16 {%0,%1,%2,%3}, [%4];"
                 : "=r"(r[0]), "=r"(r[1]), "=r"(r[2]), "=r"(r[3]) : "r"(addr));
}
__device__ __forceinline__ void cp16(uint32_t smem_dst, const void* gsrc) {
    asm volatile("cp.async.cg.shared.global [%0], [%1], 16;" :: "r"(smem_dst), "l"(gsrc));
}
#define CP_COMMIT() asm volatile("cp.async.commit_group;" ::: "memory")
#define CP_WAIT2()  asm volatile("cp.async.wait_group 2;"  ::: "memory")

// ---------------- prep kernels ----------------
__global__ void fold_weights(const float* __restrict__ Win, const float* __restrict__ Wout) {
    int j = blockIdx.x, t = blockIdx.y, d = threadIdx.x;
    const float* W = t ? Wout : Win;
    float s = 0.f;
    #pragma unroll
    for (int e = 0; e < EE; e++) s += W[(size_t)j*ED + e*DD + d];
    g_Weff[t][j*DD + d] = to_tf32(s);
}

__global__ void stack_rz(const float* __restrict__ Wr, const float* __restrict__ Wz,
                         const float* __restrict__ br, const float* __restrict__ bz,
                         const float* __restrict__ Wt) {
    int i = blockIdx.x*blockDim.x + threadIdx.x;
    if (i < 256*384) {
        int row = i / 384, col = i % 384;
        g_Wrz[i] = to_tf32((row < 128) ? Wr[row*384 + col] : Wz[(row-128)*384 + col]);
    }
    if (i < 128*384) g_WtR[i] = to_tf32(Wt[i]);
    if (i < 256) g_brz[i] = (i < 128) ? br[i] : bz[i-128];
}

// one-time: convert graph matrices to bf16 (rn)
__global__ void k_cvtA(const float* __restrict__ gin, const float* __restrict__ gout) {
    int t = blockIdx.y;
    const float* src = t ? gout : gin;
    __nv_bfloat16* dst = g_gbf + (size_t)t*MM*KGR;
    size_t i = ((size_t)blockIdx.x*blockDim.x + threadIdx.x) * 8;
    float4 f0 = *(const float4*)(src + i);
    float4 f1 = *(const float4*)(src + i + 4);
    __nv_bfloat16 h[8];
    h[0]=__float2bfloat16_rn(f0.x); h[1]=__float2bfloat16_rn(f0.y);
    h[2]=__float2bfloat16_rn(f0.z); h[3]=__float2bfloat16_rn(f0.w);
    h[4]=__float2bfloat16_rn(f1.x); h[5]=__float2bfloat16_rn(f1.y);
    h[6]=__float2bfloat16_rn(f1.z); h[7]=__float2bfloat16_rn(f1.w);
    *(uint4*)(dst + i) = *(uint4*)h;
}

// ---------------- tf32 warp-MMA core (gate kernels; unchanged from R5) ----------------
template<int KTOT>
__device__ __forceinline__ void wm_core(
    const float* __restrict__ A0, const float* __restrict__ A1, const float* __restrict__ A2,
    const float* __restrict__ Bt, int m0, int n0, float (&acc)[4][4][4])
{
    __shared__ float As[128*APAD];
    __shared__ float Bs[128*APAD];
    const int tid = threadIdx.x, lane = tid & 31, wid = tid >> 5;
    const int g = lane >> 2, tig = lane & 3;
    const int wm = wid & 1, wn = wid >> 1;
    const int r0 = tid >> 3, q4 = (tid & 7) * 4;
    constexpr int NITL = KTOT / KBLK;
    float4 pa[4], pb[4];

    auto ldtile = [&](int it) {
        int k0 = it * KBLK;
        const float* Aseg = (KTOT == 128) ? A0 : (k0 < 128 ? A0 : (k0 < 256 ? A1 : A2));
        int kl = k0 & 127;
        #pragma unroll
        for (int i = 0; i < 4; i++) {
            int r = r0 + i*32;
            pa[i] = *(const float4*)(Aseg + (size_t)(m0 + r)*DD + kl + q4);
            pb[i] = *(const float4*)(Bt + (size_t)(n0 + r)*KTOT + k0 + q4);
            pa[i].x = to_tf32(pa[i].x); pa[i].y = to_tf32(pa[i].y);
            pa[i].z = to_tf32(pa[i].z); pa[i].w = to_tf32(pa[i].w);
        }
    };
    auto sttile = [&]() {
        #pragma unroll
        for (int i = 0; i < 4; i++) {
            int r = r0 + i*32;
            *(float4*)&As[r*APAD + q4] = pa[i];
            *(float4*)&Bs[r*APAD + q4] = pb[i];
        }
    };

    ldtile(0); sttile();
    __syncthreads();

    #pragma unroll 1
    for (int it = 0; it < NITL; ++it) {
        if (it + 1 < NITL) ldtile(it + 1);
        #pragma unroll
        for (int kk = 0; kk < 4; kk++) {
            const int kb = kk*8;
            uint32_t afr[4][4], bfr[4][2];
            #pragma unroll
            for (int mf = 0; mf < 4; mf++) {
                int ar = wm*64 + mf*16 + g;
                afr[mf][0] = __float_as_uint(As[ar*APAD     + kb + tig]);
                afr[mf][1] = __float_as_uint(As[(ar+8)*APAD + kb + tig]);
                afr[mf][2] = __float_as_uint(As[ar*APAD     + kb + tig + 4]);
                afr[mf][3] = __float_as_uint(As[(ar+8)*APAD + kb + tig + 4]);
            }
            #pragma unroll
            for (int nf = 0; nf < 4; nf++) {
                int br = wn*32 + nf*8 + g;
                bfr[nf][0] = __float_as_uint(Bs[br*APAD + kb + tig]);
                bfr[nf][1] = __float_as_uint(Bs[br*APAD + kb + tig + 4]);
            }
            #pragma unroll
            for (int mf = 0; mf < 4; mf++)
                #pragma unroll
                for (int nf = 0; nf < 4; nf++)
                    mma_tf32(acc[mf][nf], afr[mf], bfr[nf]);
        }
        __syncthreads();
        if (it + 1 < NITL) { sttile(); __syncthreads(); }
    }
}

#define FRAG_SETUP() \
    const int lane = threadIdx.x & 31, wid = threadIdx.x >> 5; \
    const int g = lane >> 2, tig = lane & 3; \
    const int wm = wid & 1, wn = wid >> 1;

// ---------------- K1: gfullT = (X @ Weff^T + b) -> bf16, transposed K-major ----------------
__global__ __launch_bounds__(256) void k_gfull_mma(
    const float* __restrict__ Xext, int xsel,
    const float* __restrict__ b_in, const float* __restrict__ b_out)
{
    const float* X = state_ptr(Xext, xsel);
    const int t = blockIdx.z;
    const int m0 = blockIdx.y*128, n0 = blockIdx.x*128;
    float acc[4][4][4] = {};
    wm_core<128>(X, X, X, g_Weff[t], m0, n0, acc);

    const float* bias = t ? b_out : b_in;
    FRAG_SETUP();
    const int bb = m0 >> 10, e = n0 >> 7;
    __nv_bfloat16* outT = g_gfullT + ((size_t)t*BV + bb)*DD*KGR;
    #pragma unroll
    for (int mf = 0; mf < 4; mf++) {
        int m = m0 + wm*64 + mf*16 + g;
        int s0 = m & (SLEN-1), s1 = (m+8) & (SLEN-1);
        #pragma unroll
        for (int nf = 0; nf < 4; nf++) {
            int n = n0 + wn*32 + nf*8 + 2*tig;
            int d0 = n & 127, d1 = (n+1) & 127;
            outT[(size_t)d0*KGR + s0*4 + e] = __float2bfloat16_rn(acc[mf][nf][0] + bias[n]);
            outT[(size_t)d1*KGR + s0*4 + e] = __float2bfloat16_rn(acc[mf][nf][1] + bias[n+1]);
            outT[(size_t)d0*KGR + s1*4 + e] = __float2bfloat16_rn(acc[mf][nf][2] + bias[n]);
            outT[(size_t)d1*KGR + s1*4 + e] = __float2bfloat16_rn(acc[mf][nf][3] + bias[n+1]);
        }
    }
}

// ---------------- K2: graph GEMM, bf16 mma + 4-stage cp.async + ldmatrix ----------------
// C[b,t][1024,128] = Abf[1024,4096] @ gfullT[b,t]^T
__global__ __launch_bounds__(256) void k_graph_bf16(int dummy)
{
    extern __shared__ char dsm[];
    const uint32_t sb = (uint32_t)__cvta_generic_to_shared(dsm);
    const int tid = threadIdx.x, lane = tid & 31, wid = tid >> 5;
    const int l8 = lane & 7, q = lane >> 3;
    const int wm = wid & 1, wn = wid >> 1;
    const int bt = blockIdx.y, t = bt & 1, b = bt >> 1;
    const int m0 = blockIdx.x * 128;

    const __nv_bfloat16* A  = g_gbf + (size_t)t*MM*KGR + (size_t)b*SLEN*KGR;
    const __nv_bfloat16* Bg = g_gfullT + ((size_t)t*BV + b)*DD*KGR;
    float* C = g_gsum[t] + (size_t)b*SLEN*DD;

    // cp.async chunk mapping: 1024 16B-chunks per operand tile; 4 per thread
    auto issue = [&](int stg, int k0) {
        uint32_t base = sb + stg*STG_BYTES;
        #pragma unroll
        for (int i = 0; i < 4; i++) {
            int c = tid + i*256;
            int row = c >> 3, off = c & 7;
            cp16(base + row*144 + off*16,              A  + (size_t)(m0+row)*KGR + k0 + off*8);
            cp16(base + TILE_BYTES + row*144 + off*16, Bg + (size_t)row*KGR + k0 + off*8);
        }
    };

    float acc[4][4][4] = {};

    // prologue: stages 0..2
    #pragma unroll
    for (int s = 0; s < GSTG-1; s++) { issue(s, s*KB2); CP_COMMIT(); }

    #pragma unroll 1
    for (int it = 0; it < NIT2; ++it) {
        CP_WAIT2();
        __syncthreads();
        if (it + GSTG-1 < NIT2) issue((it + GSTG-1) & (GSTG-1), (it + GSTG-1)*KB2);
        CP_COMMIT();

        const uint32_t sA = sb + (it & (GSTG-1))*STG_BYTES;
        const uint32_t sB = sA + TILE_BYTES;
        #pragma unroll
        for (int kk = 0; kk < 4; kk++) {
            uint32_t afr[4][4], bfr[4][2];
            #pragma unroll
            for (int mf = 0; mf < 4; mf++) {
                int row = wm*64 + mf*16 + (q & 1)*8 + l8;
                ldm_x4(afr[mf], sA + row*144 + kk*32 + (q >> 1)*16);
            }
            #pragma unroll
            for (int h = 0; h < 2; h++) {
                uint32_t r[4];
                int row = wn*32 + h*16 + (q >> 1)*8 + l8;
                ldm_x4(r, sB + row*144 + kk*32 + (q & 1)*16);
                bfr[2*h][0] = r[0]; bfr[2*h][1] = r[1];
                bfr[2*h+1][0] = r[2]; bfr[2*h+1][1] = r[3];
            }
            #pragma unroll
            for (int mf = 0; mf < 4; mf++)
                #pragma unroll
                for (int nf = 0; nf < 4; nf++)
                    mma_bf16(acc[mf][nf], afr[mf], bfr[nf]);
        }
    }

    // epilogue (same fragment->C mapping as tf32 path: m16n8 D layout)
    const int g = lane >> 2, tig = lane & 3;
    #pragma unroll
    for (int mf = 0; mf < 4; mf++) {
        int m = m0 + wm*64 + mf*16 + g;
        #pragma unroll
        for (int nf = 0; nf < 4; nf++) {
            int n = wn*32 + nf*8 + 2*tig;
            float2 v0 = {acc[mf][nf][0], acc[mf][nf][1]};
            float2 v1 = {acc[mf][nf][2], acc[mf][nf][3]};
            *(float2*)(C + (size_t)m*DD + n)     = v0;
            *(float2*)(C + (size_t)(m+8)*DD + n) = v1;
        }
    }
}

// ---------------- K3a: r,z = sigmoid([gi,go,X] @ [Wr;Wz]^T + b); rg = r*X ----------------
__global__ __launch_bounds__(256) void k_rz_mma(const float* __restrict__ Xext, int xsel)
{
    const float* X = state_ptr(Xext, xsel);
    const int m0 = blockIdx.y*128, n0 = blockIdx.x*128;
    float acc[4][4][4] = {};
    wm_core<384>(g_gsum[0], g_gsum[1], X, g_Wrz, m0, n0, acc);

    FRAG_SETUP();
    #pragma unroll
    for (int mf = 0; mf < 4; mf++) {
        int m = m0 + wm*64 + mf*16 + g;
        #pragma unroll
        for (int nf = 0; nf < 4; nf++) {
            int n = n0 + wn*32 + nf*8 + 2*tig;
            #pragma unroll
            for (int v = 0; v < 4; v++) {
                int mm = (v < 2) ? m : m + 8;
                int nn = n + (v & 1);
                float s = 1.f/(1.f + expf(-(acc[mf][nf][v] + g_brz[nn])));
                if (n0 == 0)
                    g_rg[(size_t)mm*DD + nn] = s * X[(size_t)mm*DD + nn];
                else
                    g_z[(size_t)mm*DD + (nn - 128)] = s;
            }
        }
    }
}

// ---------------- K3b: h = tanh([gi,go,rg] @ Wt^T + bt); out = (1-z)*X + z*h ----------------
__global__ __launch_bounds__(256) void k_update_mma(
    const float* __restrict__ Xext, int xsel,
    const float* __restrict__ bt,
    float* __restrict__ extOut, int osel)
{
    const float* X = state_ptr(Xext, xsel);
    float* out = (osel == 0) ? g_stateA : (osel == 1 ? g_stateB : extOut);
    const int m0 = blockIdx.y*128;
    float acc[4][4][4] = {};
    wm_core<384>(g_gsum[0], g_gsum[1], g_rg, g_WtR, m0, 0, acc);

    FRAG_SETUP();
    #pragma unroll
    for (int mf = 0; mf < 4; mf++) {
        int m = m0 + wm*64 + mf*16 + g;
        #pragma unroll
        for (int nf = 0; nf < 4; nf++) {
            int n = wn*32 + nf*8 + 2*tig;
            #pragma unroll
            for (int v = 0; v < 4; v++) {
                int mm = (v < 2) ? m : m + 8;
                int nn = n + (v & 1);
                float h = tanhf(acc[mf][nf][v] + bt[nn]);
                float zv = g_z[(size_t)mm*DD + nn];
                float xv = X[(size_t)mm*DD + nn];
                out[(size_t)mm*DD + nn] = (1.f - zv)*xv + zv*h;
            }
        }
    }
}

// ---------------- launch ----------------
extern "C" void kernel_launch(void* const* d_in, const int* in_sizes, int n_in,
                              void* d_out, int out_size)
{
    const float* input = (const float*)d_in[0];
    const float* gin   = (const float*)d_in[1];
    const float* gout  = (const float*)d_in[2];
    const float* W_in  = (const float*)d_in[3];
    const float* b_in  = (const float*)d_in[4];
    const float* W_out = (const float*)d_in[5];
    const float* b_out = (const float*)d_in[6];
    const float* W_r   = (const float*)d_in[7];
    const float* b_r   = (const float*)d_in[8];
    const float* W_z   = (const float*)d_in[9];
    const float* b_z   = (const float*)d_in[10];
    const float* W_t   = (const float*)d_in[11];
    const float* b_t   = (const float*)d_in[12];

    cudaFuncSetAttribute(k_graph_bf16, cudaFuncAttributeMaxDynamicSharedMemorySize, GSMEM);

    fold_weights<<<dim3(ED, 2), DD>>>(W_in, W_out);
    stack_rz<<<(256*384 + 255)/256, 256>>>(W_r, W_z, b_r, b_z, W_t);
    k_cvtA<<<dim3((MM/8)*(KGR/256), 2), 256>>>(gin, gout);   // 16384 x 2 blocks

    int xsel = 2;                       // 2 => external pointer (batchinput)
    for (int s = 0; s < NSTEPS; s++) {
        int osel = (s == NSTEPS-1) ? 2 : (s & 1);
        k_gfull_mma <<<dim3(4, 64, 2), 256>>>(input, xsel, b_in, b_out);
        k_graph_bf16<<<dim3(8, 16), 256, GSMEM>>>(0);
        k_rz_mma    <<<dim3(2, 64), 256>>>(input, xsel);
        k_update_mma<<<dim3(1, 64), 256>>>(input, xsel, b_t, (float*)d_out, osel);
        xsel = osel;
    }
}

// round 8
// speedup vs baseline: 6.4441x; 1.1085x over previous
#include <cuda_runtime.h>
#include <cuda_fp16.h>
#include <math.h>
#include <stdint.h>

#define BV 8
#define SLEN 1024
#define DD 128
#define EE 4
#define ED 512
#define MM (BV*SLEN)          // 8192 rows
#define KGR (SLEN*EE)         // 4096 graph K
#define NSTEPS 5

#define KB2 64                    // fp16 K per stage (128B rows)
#define ROWB 72                   // fp16 elems per smem row (144B stride)
#define TILE_BYTES (128*ROWB*2)   // 18432 B per operand tile
#define STG_BYTES (2*TILE_BYTES)  // A+B per stage
#define GSMEM4 (4*STG_BYTES)      // 147456 B (graph)
#define GSMEM2 (2*STG_BYTES)      // 73728 B (gates)

typedef __half fp16;

// ---------------- device scratch (no allocation allowed) ----------------
__device__ fp16 g_WeffH[2][ED*DD];        // folded W_in/W_out [512,128] fp16
__device__ fp16 g_WrzH[256*384];          // stacked [W_r; W_z] fp16
__device__ fp16 g_WtH[128*384];           // W_t fp16
__device__ float g_brz[256];
__device__ fp16 g_gh[(size_t)2*MM*KGR];       // fp16 gin/gout (134MB)
__device__ fp16 g_gfullT[(size_t)2*BV*DD*KGR];// [t][b][d=128][k=4096] fp16 K-major
__device__ fp16 g_gsumH[2][MM*DD];        // gi / go fp16 (GEMM A operand only)
__device__ fp16 g_rgH[MM*DD];             // r * out, fp16 (A operand only)
__device__ fp16 g_stateH[MM*DD];          // fp16 shadow of state (A operand)
__device__ float g_z[MM*DD];              // z (fp32, blend)
__device__ float g_stateA[MM*DD];
__device__ float g_stateB[MM*DD];

__device__ __forceinline__ const float* state_ptr(const float* ext, int sel) {
    return sel == 0 ? g_stateA : (sel == 1 ? g_stateB : ext);
}

// fp16 warp MMA, fp32 accumulate
__device__ __forceinline__ void mma_f16(float* d, const uint32_t* a, const uint32_t* b) {
    asm volatile(
        "mma.sync.aligned.m16n8k16.row.col.f32.f16.f16.f32 "
        "{%0,%1,%2,%3}, {%4,%5,%6,%7}, {%8,%9}, {%0,%1,%2,%3};"
        : "+f"(d[0]), "+f"(d[1]), "+f"(d[2]), "+f"(d[3])
        : "r"(a[0]), "r"(a[1]), "r"(a[2]), "r"(a[3]), "r"(b[0]), "r"(b[1]));
}
__device__ __forceinline__ void ldm_x4(uint32_t* r, uint32_t addr) {
    asm volatile("ldmatrix.sync.aligned.m8n8.x4.shared.b16 {%0,%1,%2,%3}, [%4];"
                 : "=r"(r[0]), "=r"(r[1]), "=r"(r[2]), "=r"(r[3]) : "r"(addr));
}
__device__ __forceinline__ void cp16(uint32_t smem_dst, const void* gsrc) {
    asm volatile("cp.async.cg.shared.global [%0], [%1], 16;" :: "r"(smem_dst), "l"(gsrc));
}
#define CP_COMMIT() asm volatile("cp.async.commit_group;" ::: "memory")

// ---------------- unified fp16 GEMM core ----------------
// C_tile[128 x 128] at (m0, n0): A rows from (up to 3) [M, LDA] fp16 segments
// (segmented iff KTOT > LDA), Bt = [N, KTOT] fp16 row-major (K-contiguous).
template<int KTOT, int LDA, int NSTG>
__device__ __forceinline__ void h_core(
    const fp16* __restrict__ A0, const fp16* __restrict__ A1, const fp16* __restrict__ A2,
    const fp16* __restrict__ Bt, int m0, int n0, float (&acc)[4][4][4], char* dsm)
{
    const uint32_t sb = (uint32_t)__cvta_generic_to_shared(dsm);
    const int tid = threadIdx.x, lane = tid & 31, wid = tid >> 5;
    const int l8 = lane & 7, q = lane >> 3;
    const int wm = wid & 1, wn = wid >> 1;
    constexpr int NITL = KTOT / KB2;

    auto issue = [&](int stg, int k0) {
        if (k0 < KTOT) {
            const fp16* Aseg; int kl;
            if (KTOT > LDA) {           // 3 x 128-wide segments
                Aseg = (k0 < 128) ? A0 : (k0 < 256 ? A1 : A2);
                kl = k0 & 127;
            } else { Aseg = A0; kl = k0; }
            uint32_t base = sb + stg*STG_BYTES;
            #pragma unroll
            for (int i = 0; i < 4; i++) {
                int c = tid + i*256, row = c >> 3, off = c & 7;
                cp16(base + row*144 + off*16,
                     Aseg + (size_t)(m0+row)*LDA + kl + off*8);
                cp16(base + TILE_BYTES + row*144 + off*16,
                     Bt + (size_t)(n0+row)*KTOT + k0 + off*8);
            }
        }
        CP_COMMIT();
    };

    #pragma unroll
    for (int s = 0; s < NSTG-1; s++) issue(s, s*KB2);

    #pragma unroll 1
    for (int it = 0; it < NITL; ++it) {
        asm volatile("cp.async.wait_group %0;" :: "n"(NSTG-2) : "memory");
        __syncthreads();
        issue((it + NSTG-1) & (NSTG-1), (it + NSTG-1)*KB2);

        const uint32_t sA = sb + (it & (NSTG-1))*STG_BYTES;
        const uint32_t sB = sA + TILE_BYTES;
        #pragma unroll
        for (int kk = 0; kk < 4; kk++) {
            uint32_t afr[4][4], bfr[4][2];
            #pragma unroll
            for (int mf = 0; mf < 4; mf++) {
                int row = wm*64 + mf*16 + (q & 1)*8 + l8;
                ldm_x4(afr[mf], sA + row*144 + kk*32 + (q >> 1)*16);
            }
            #pragma unroll
            for (int h = 0; h < 2; h++) {
                uint32_t r[4];
                int row = wn*32 + h*16 + (q >> 1)*8 + l8;
                ldm_x4(r, sB + row*144 + kk*32 + (q & 1)*16);
                bfr[2*h][0] = r[0]; bfr[2*h][1] = r[1];
                bfr[2*h+1][0] = r[2]; bfr[2*h+1][1] = r[3];
            }
            #pragma unroll
            for (int mf = 0; mf < 4; mf++)
                #pragma unroll
                for (int nf = 0; nf < 4; nf++)
                    mma_f16(acc[mf][nf], afr[mf], bfr[nf]);
        }
    }
}

#define FRAG_SETUP() \
    const int lane = threadIdx.x & 31, wid = threadIdx.x >> 5; \
    const int g = lane >> 2, tig = lane & 3; \
    const int wm = wid & 1, wn = wid >> 1;

// ---------------- prep kernels ----------------
__global__ void fold_weights(const float* __restrict__ Win, const float* __restrict__ Wout) {
    int j = blockIdx.x, t = blockIdx.y, d = threadIdx.x;
    const float* W = t ? Wout : Win;
    float s = 0.f;
    #pragma unroll
    for (int e = 0; e < EE; e++) s += W[(size_t)j*ED + e*DD + d];
    g_WeffH[t][j*DD + d] = __float2half_rn(s);
}

__global__ void stack_rzt(const float* __restrict__ Wr, const float* __restrict__ Wz,
                          const float* __restrict__ br, const float* __restrict__ bz,
                          const float* __restrict__ Wt) {
    int i = blockIdx.x*blockDim.x + threadIdx.x;
    if (i < 256*384) {
        int row = i / 384, col = i % 384;
        g_WrzH[i] = __float2half_rn((row < 128) ? Wr[row*384 + col]
                                                : Wz[(row-128)*384 + col]);
    }
    if (i < 128*384) g_WtH[i] = __float2half_rn(Wt[i]);
    if (i < 256) g_brz[i] = (i < 128) ? br[i] : bz[i-128];
}

__global__ void k_cvtA(const float* __restrict__ gin, const float* __restrict__ gout) {
    int t = blockIdx.y;
    const float* src = t ? gout : gin;
    fp16* dst = g_gh + (size_t)t*MM*KGR;
    size_t i = ((size_t)blockIdx.x*blockDim.x + threadIdx.x) * 8;
    float4 f0 = *(const float4*)(src + i);
    float4 f1 = *(const float4*)(src + i + 4);
    fp16 h[8];
    h[0]=__float2half_rn(f0.x); h[1]=__float2half_rn(f0.y);
    h[2]=__float2half_rn(f0.z); h[3]=__float2half_rn(f0.w);
    h[4]=__float2half_rn(f1.x); h[5]=__float2half_rn(f1.y);
    h[6]=__float2half_rn(f1.z); h[7]=__float2half_rn(f1.w);
    *(uint4*)(dst + i) = *(uint4*)h;
}

__global__ void k_cvtX(const float* __restrict__ x) {
    size_t i = ((size_t)blockIdx.x*blockDim.x + threadIdx.x) * 4;
    float4 f = *(const float4*)(x + i);
    fp16 h[4];
    h[0]=__float2half_rn(f.x); h[1]=__float2half_rn(f.y);
    h[2]=__float2half_rn(f.z); h[3]=__float2half_rn(f.w);
    *(uint2*)(g_stateH + i) = *(uint2*)h;
}

// ---------------- K1: gfullT = (XH @ WeffH^T + b) -> fp16, transposed K-major ----------------
__global__ __launch_bounds__(256) void k_gfull_h(
    const float* __restrict__ b_in, const float* __restrict__ b_out)
{
    extern __shared__ char dsm[];
    const int t = blockIdx.z;
    const int m0 = blockIdx.y*128, n0 = blockIdx.x*128;
    float acc[4][4][4] = {};
    h_core<128, 128, 2>(g_stateH, g_stateH, g_stateH, g_WeffH[t], m0, n0, acc, dsm);

    const float* bias = t ? b_out : b_in;
    FRAG_SETUP();
    const int bb = m0 >> 10, e = n0 >> 7;
    fp16* outT = g_gfullT + ((size_t)t*BV + bb)*DD*KGR;
    #pragma unroll
    for (int mf = 0; mf < 4; mf++) {
        int m = m0 + wm*64 + mf*16 + g;
        int s0 = m & (SLEN-1), s1 = (m+8) & (SLEN-1);
        #pragma unroll
        for (int nf = 0; nf < 4; nf++) {
            int n = n0 + wn*32 + nf*8 + 2*tig;
            int d0 = n & 127, d1 = (n+1) & 127;
            outT[(size_t)d0*KGR + s0*4 + e] = __float2half_rn(acc[mf][nf][0] + bias[n]);
            outT[(size_t)d1*KGR + s0*4 + e] = __float2half_rn(acc[mf][nf][1] + bias[n+1]);
            outT[(size_t)d0*KGR + s1*4 + e] = __float2half_rn(acc[mf][nf][2] + bias[n]);
            outT[(size_t)d1*KGR + s1*4 + e] = __float2half_rn(acc[mf][nf][3] + bias[n+1]);
        }
    }
}

// ---------------- K2: graph GEMM ----------------
__global__ __launch_bounds__(256) void k_graph_h(int dummy)
{
    extern __shared__ char dsm[];
    const int bt = blockIdx.y, t = bt & 1, b = bt >> 1;
    const int m0 = blockIdx.x * 128;
    const fp16* A  = g_gh + (size_t)t*MM*KGR + (size_t)b*SLEN*KGR;
    const fp16* Bg = g_gfullT + ((size_t)t*BV + b)*DD*KGR;
    fp16* C = g_gsumH[t] + (size_t)b*SLEN*DD;

    float acc[4][4][4] = {};
    h_core<KGR, KGR, 4>(A, A, A, Bg, m0, 0, acc, dsm);

    FRAG_SETUP();
    #pragma unroll
    for (int mf = 0; mf < 4; mf++) {
        int m = m0 + wm*64 + mf*16 + g;
        #pragma unroll
        for (int nf = 0; nf < 4; nf++) {
            int n = wn*32 + nf*8 + 2*tig;
            fp16 p0[2] = {__float2half_rn(acc[mf][nf][0]), __float2half_rn(acc[mf][nf][1])};
            fp16 p1[2] = {__float2half_rn(acc[mf][nf][2]), __float2half_rn(acc[mf][nf][3])};
            *(uint32_t*)(C + (size_t)m*DD + n)     = *(uint32_t*)p0;
            *(uint32_t*)(C + (size_t)(m+8)*DD + n) = *(uint32_t*)p1;
        }
    }
}

// ---------------- K3a: r,z = sigmoid([gi,go,X] @ [Wr;Wz]^T + b); rgH = fp16(r*X) ----------------
__global__ __launch_bounds__(256) void k_rz_h(const float* __restrict__ Xext, int xsel)
{
    extern __shared__ char dsm[];
    const float* X = state_ptr(Xext, xsel);
    const int m0 = blockIdx.y*128, n0 = blockIdx.x*128;   // n0 in {0,128}
    float acc[4][4][4] = {};
    h_core<384, 128, 2>(g_gsumH[0], g_gsumH[1], g_stateH, g_WrzH, m0, n0, acc, dsm);

    FRAG_SETUP();
    #pragma unroll
    for (int mf = 0; mf < 4; mf++) {
        int m = m0 + wm*64 + mf*16 + g;
        #pragma unroll
        for (int nf = 0; nf < 4; nf++) {
            int n = n0 + wn*32 + nf*8 + 2*tig;
            #pragma unroll
            for (int v = 0; v < 4; v++) {
                int mm = (v < 2) ? m : m + 8;
                int nn = n + (v & 1);
                float s = 1.f/(1.f + expf(-(acc[mf][nf][v] + g_brz[nn])));
                if (n0 == 0)
                    g_rgH[(size_t)mm*DD + nn] =
                        __float2half_rn(s * X[(size_t)mm*DD + nn]);
                else
                    g_z[(size_t)mm*DD + (nn - 128)] = s;
            }
        }
    }
}

// ---------------- K3b: h = tanh([gi,go,rg] @ Wt^T + bt); out = (1-z)*X + z*h ----------------
__global__ __launch_bounds__(256) void k_update_h(
    const float* __restrict__ Xext, int xsel,
    const float* __restrict__ bt,
    float* __restrict__ extOut, int osel)
{
    extern __shared__ char dsm[];
    const float* X = state_ptr(Xext, xsel);
    float* out = (osel == 0) ? g_stateA : (osel == 1 ? g_stateB : extOut);
    const int m0 = blockIdx.y*128;
    float acc[4][4][4] = {};
    h_core<384, 128, 2>(g_gsumH[0], g_gsumH[1], g_rgH, g_WtH, m0, 0, acc, dsm);

    FRAG_SETUP();
    #pragma unroll
    for (int mf = 0; mf < 4; mf++) {
        int m = m0 + wm*64 + mf*16 + g;
        #pragma unroll
        for (int nf = 0; nf < 4; nf++) {
            int n = wn*32 + nf*8 + 2*tig;
            #pragma unroll
            for (int v = 0; v < 4; v++) {
                int mm = (v < 2) ? m : m + 8;
                int nn = n + (v & 1);
                float h = tanhf(acc[mf][nf][v] + bt[nn]);
                float zv = g_z[(size_t)mm*DD + nn];
                float xv = X[(size_t)mm*DD + nn];
                float o = (1.f - zv)*xv + zv*h;
                out[(size_t)mm*DD + nn] = o;
                g_stateH[(size_t)mm*DD + nn] = __float2half_rn(o);
            }
        }
    }
}

// ---------------- launch ----------------
extern "C" void kernel_launch(void* const* d_in, const int* in_sizes, int n_in,
                              void* d_out, int out_size)
{
    const float* input = (const float*)d_in[0];
    const float* gin   = (const float*)d_in[1];
    const float* gout  = (const float*)d_in[2];
    const float* W_in  = (const float*)d_in[3];
    const float* b_in  = (const float*)d_in[4];
    const float* W_out = (const float*)d_in[5];
    const float* b_out = (const float*)d_in[6];
    const float* W_r   = (const float*)d_in[7];
    const float* b_r   = (const float*)d_in[8];
    const float* W_z   = (const float*)d_in[9];
    const float* b_z   = (const float*)d_in[10];
    const float* W_t   = (const float*)d_in[11];
    const float* b_t   = (const float*)d_in[12];

    cudaFuncSetAttribute(k_graph_h,  cudaFuncAttributeMaxDynamicSharedMemorySize, GSMEM4);
    cudaFuncSetAttribute(k_gfull_h,  cudaFuncAttributeMaxDynamicSharedMemorySize, GSMEM2);
    cudaFuncSetAttribute(k_rz_h,     cudaFuncAttributeMaxDynamicSharedMemorySize, GSMEM2);
    cudaFuncSetAttribute(k_update_h, cudaFuncAttributeMaxDynamicSharedMemorySize, GSMEM2);

    fold_weights<<<dim3(ED, 2), DD>>>(W_in, W_out);
    stack_rzt<<<(256*384 + 255)/256, 256>>>(W_r, W_z, b_r, b_z, W_t);
    k_cvtA<<<dim3((MM/8)*(KGR/256), 2), 256>>>(gin, gout);
    k_cvtX<<<(MM*DD/4 + 255)/256, 256>>>(input);

    int xsel = 2;                       // fp32 state: 2 => external (batchinput)
    for (int s = 0; s < NSTEPS; s++) {
        int osel = (s == NSTEPS-1) ? 2 : (s & 1);
        k_gfull_h <<<dim3(4, 64, 2), 256, GSMEM2>>>(b_in, b_out);
        k_graph_h <<<dim3(8, 16), 256, GSMEM4>>>(0);
        k_rz_h    <<<dim3(2, 64), 256, GSMEM2>>>(input, xsel);
        k_update_h<<<dim3(1, 64), 256, GSMEM2>>>(input, xsel, b_t, (float*)d_out, osel);
        xsel = osel;
    }
}

// round 9
// speedup vs baseline: 7.5770x; 1.1758x over previous
#include <cuda_runtime.h>
#include <cuda_fp16.h>
#include <math.h>
#include <stdint.h>

#define BV 8
#define SLEN 1024
#define DD 128
#define EE 4
#define ED 512
#define MM (BV*SLEN)          // 8192 rows
#define KGR (SLEN*EE)         // 4096 graph K
#define NSTEPS 5
#define KB2 64                // K elems per pipeline stage (128B rows)

typedef __half fp16;

// smem per stage: (MTILE + 128) rows x 144 B
#define SM_GR (3*(128+128)*144)   // graph: M128, 3 stages = 110592
#define SM_GF (2*(128+128)*144)   // gfull: M128, 2 stages = 73728
#define SM_64 (2*(64+128)*144)    // rz/update: M64, 2 stages = 55296

// ---------------- device scratch (no allocation allowed) ----------------
__device__ fp16 g_WeffH[2][ED*DD];        // folded W_in/W_out [512,128] fp16
__device__ fp16 g_WrzH[256*384];          // stacked [W_r; W_z] fp16
__device__ fp16 g_WtH[128*384];           // W_t fp16
__device__ float g_brz[256];
__device__ fp16 g_gh[(size_t)2*MM*KGR];       // fp16 gin/gout (134MB)
__device__ fp16 g_gfullT[(size_t)2*BV*DD*KGR];// [t][b][d=128][k=4096] fp16 K-major
__device__ float g_gpart[(size_t)2*2*MM*DD];  // split-K partials [ks][t][m][d] (32MB)
__device__ fp16 g_gsumH[2][MM*DD];        // gi / go fp16 (GEMM A operand)
__device__ fp16 g_rgH[MM*DD];             // r * out, fp16
__device__ fp16 g_stateH[MM*DD];          // fp16 shadow of state
__device__ float g_z[MM*DD];              // z (fp32, blend)
__device__ float g_stateA[MM*DD];
__device__ float g_stateB[MM*DD];

__device__ __forceinline__ const float* state_ptr(const float* ext, int sel) {
    return sel == 0 ? g_stateA : (sel == 1 ? g_stateB : ext);
}

__device__ __forceinline__ void mma_f16(float* d, const uint32_t* a, const uint32_t* b) {
    asm volatile(
        "mma.sync.aligned.m16n8k16.row.col.f32.f16.f16.f32 "
        "{%0,%1,%2,%3}, {%4,%5,%6,%7}, {%8,%9}, {%0,%1,%2,%3};"
        : "+f"(d[0]), "+f"(d[1]), "+f"(d[2]), "+f"(d[3])
        : "r"(a[0]), "r"(a[1]), "r"(a[2]), "r"(a[3]), "r"(b[0]), "r"(b[1]));
}
__device__ __forceinline__ void ldm_x4(uint32_t* r, uint32_t addr) {
    asm volatile("ldmatrix.sync.aligned.m8n8.x4.shared.b16 {%0,%1,%2,%3}, [%4];"
                 : "=r"(r[0]), "=r"(r[1]), "=r"(r[2]), "=r"(r[3]) : "r"(addr));
}
__device__ __forceinline__ void cp16(uint32_t smem_dst, const void* gsrc) {
    asm volatile("cp.async.cg.shared.global [%0], [%1], 16;" :: "r"(smem_dst), "l"(gsrc));
}
#define CP_COMMIT() asm volatile("cp.async.commit_group;" ::: "memory")

// ---------------- unified fp16 GEMM core ----------------
// C_tile[MTILE x 128] at (m0, n0). A rows from up to 3 [M, LDA] segments
// (segmented iff KTOT > LDA). Bt = [N, LDB] fp16, K-contiguous rows.
// NFRAG = 128 / (warp_n_count * 8).
template<int KTOT, int LDA, int LDB, int NSTG, int MTILE, int NFRAG>
__device__ __forceinline__ void h_core(
    const fp16* __restrict__ A0, const fp16* __restrict__ A1, const fp16* __restrict__ A2,
    const fp16* __restrict__ Bt, int m0, int n0, float (&acc)[4][NFRAG][4], char* dsm)
{
    constexpr int ATILE_B = MTILE*144;
    constexpr int STGB = ATILE_B + 128*144;
    constexpr int NITL = KTOT / KB2;
    constexpr int WMc = MTILE/64;          // 2 (M128) or 1 (M64)
    const uint32_t sb = (uint32_t)__cvta_generic_to_shared(dsm);
    const int tid = threadIdx.x, lane = tid & 31, wid = tid >> 5;
    const int l8 = lane & 7, q = lane >> 3;
    const int wm = (WMc == 2) ? (wid & 1) : 0;
    const int wn = (WMc == 2) ? (wid >> 1) : wid;

    auto issue = [&](int stg, int k0) {
        if (k0 < KTOT) {
            const fp16* Aseg; int kl;
            if (KTOT > LDA) {              // 3 x 128-wide segments
                Aseg = (k0 < 128) ? A0 : (k0 < 256 ? A1 : A2);
                kl = k0 & 127;
            } else { Aseg = A0; kl = k0; }
            uint32_t base = sb + stg*STGB;
            #pragma unroll
            for (int i = 0; i < MTILE*8/256; i++) {
                int c = tid + i*256, row = c >> 3, off = c & 7;
                cp16(base + row*144 + off*16,
                     Aseg + (size_t)(m0+row)*LDA + kl + off*8);
            }
            #pragma unroll
            for (int i = 0; i < 4; i++) {
                int c = tid + i*256, row = c >> 3, off = c & 7;
                cp16(base + ATILE_B + row*144 + off*16,
                     Bt + (size_t)(n0+row)*LDB + k0 + off*8);
            }
        }
        CP_COMMIT();
    };

    #pragma unroll
    for (int s = 0; s < NSTG-1; s++) issue(s, s*KB2);

    #pragma unroll 1
    for (int it = 0; it < NITL; ++it) {
        asm volatile("cp.async.wait_group %0;" :: "n"(NSTG-2) : "memory");
        __syncthreads();
        issue((it + NSTG-1) % NSTG, (it + NSTG-1)*KB2);

        const uint32_t sA = sb + (it % NSTG)*STGB;
        const uint32_t sB = sA + ATILE_B;
        #pragma unroll
        for (int kk = 0; kk < 4; kk++) {
            uint32_t afr[4][4], bfr[NFRAG][2];
            #pragma unroll
            for (int mf = 0; mf < 4; mf++) {
                int row = wm*64 + mf*16 + (q & 1)*8 + l8;
                ldm_x4(afr[mf], sA + row*144 + kk*32 + (q >> 1)*16);
            }
            #pragma unroll
            for (int h = 0; h < NFRAG/2; h++) {
                uint32_t r[4];
                int row = wn*(8*NFRAG) + h*16 + (q >> 1)*8 + l8;
                ldm_x4(r, sB + row*144 + kk*32 + (q & 1)*16);
                bfr[2*h][0] = r[0]; bfr[2*h][1] = r[1];
                bfr[2*h+1][0] = r[2]; bfr[2*h+1][1] = r[3];
            }
            #pragma unroll
            for (int mf = 0; mf < 4; mf++)
                #pragma unroll
                for (int nf = 0; nf < NFRAG; nf++)
                    mma_f16(acc[mf][nf], afr[mf], bfr[nf]);
        }
    }
}

// ---------------- prep kernels ----------------
__global__ void fold_weights(const float* __restrict__ Win, const float* __restrict__ Wout) {
    int j = blockIdx.x, t = blockIdx.y, d = threadIdx.x;
    const float* W = t ? Wout : Win;
    float s = 0.f;
    #pragma unroll
    for (int e = 0; e < EE; e++) s += W[(size_t)j*ED + e*DD + d];
    g_WeffH[t][j*DD + d] = __float2half_rn(s);
}

__global__ void stack_rzt(const float* __restrict__ Wr, const float* __restrict__ Wz,
                          const float* __restrict__ br, const float* __restrict__ bz,
                          const float* __restrict__ Wt) {
    int i = blockIdx.x*blockDim.x + threadIdx.x;
    if (i < 256*384) {
        int row = i / 384, col = i % 384;
        g_WrzH[i] = __float2half_rn((row < 128) ? Wr[row*384 + col]
                                                : Wz[(row-128)*384 + col]);
    }
    if (i < 128*384) g_WtH[i] = __float2half_rn(Wt[i]);
    if (i < 256) g_brz[i] = (i < 128) ? br[i] : bz[i-128];
}

__global__ void k_cvtA(const float* __restrict__ gin, const float* __restrict__ gout) {
    int t = blockIdx.y;
    const float* src = t ? gout : gin;
    fp16* dst = g_gh + (size_t)t*MM*KGR;
    size_t i = ((size_t)blockIdx.x*blockDim.x + threadIdx.x) * 8;
    float4 f0 = *(const float4*)(src + i);
    float4 f1 = *(const float4*)(src + i + 4);
    fp16 h[8];
    h[0]=__float2half_rn(f0.x); h[1]=__float2half_rn(f0.y);
    h[2]=__float2half_rn(f0.z); h[3]=__float2half_rn(f0.w);
    h[4]=__float2half_rn(f1.x); h[5]=__float2half_rn(f1.y);
    h[6]=__float2half_rn(f1.z); h[7]=__float2half_rn(f1.w);
    *(uint4*)(dst + i) = *(uint4*)h;
}

__global__ void k_cvtX(const float* __restrict__ x) {
    size_t i = ((size_t)blockIdx.x*blockDim.x + threadIdx.x) * 4;
    float4 f = *(const float4*)(x + i);
    fp16 h[4];
    h[0]=__float2half_rn(f.x); h[1]=__float2half_rn(f.y);
    h[2]=__float2half_rn(f.z); h[3]=__float2half_rn(f.w);
    *(uint2*)(g_stateH + i) = *(uint2*)h;
}

// ---------------- K1: gfullT = (XH @ WeffH^T + b) -> fp16 transposed (M128, 2 stages) ----------------
__global__ __launch_bounds__(256) void k_gfull_h(
    const float* __restrict__ b_in, const float* __restrict__ b_out)
{
    extern __shared__ char dsm[];
    const int t = blockIdx.z;
    const int m0 = blockIdx.y*128, n0 = blockIdx.x*128;
    float acc[4][4][4] = {};
    h_core<128,128,128,2,128,4>(g_stateH, g_stateH, g_stateH, g_WeffH[t], m0, n0, acc, dsm);

    const float* bias = t ? b_out : b_in;
    const int lane = threadIdx.x & 31, wid = threadIdx.x >> 5;
    const int g = lane >> 2, tig = lane & 3;
    const int wm = wid & 1, wn = wid >> 1;
    const int bb = m0 >> 10, e = n0 >> 7;
    fp16* outT = g_gfullT + ((size_t)t*BV + bb)*DD*KGR;
    #pragma unroll
    for (int mf = 0; mf < 4; mf++) {
        int m = m0 + wm*64 + mf*16 + g;
        int s0 = m & (SLEN-1), s1 = (m+8) & (SLEN-1);
        #pragma unroll
        for (int nf = 0; nf < 4; nf++) {
            int n = n0 + wn*32 + nf*8 + 2*tig;
            int d0 = n & 127, d1 = (n+1) & 127;
            outT[(size_t)d0*KGR + s0*4 + e] = __float2half_rn(acc[mf][nf][0] + bias[n]);
            outT[(size_t)d1*KGR + s0*4 + e] = __float2half_rn(acc[mf][nf][1] + bias[n+1]);
            outT[(size_t)d0*KGR + s1*4 + e] = __float2half_rn(acc[mf][nf][2] + bias[n]);
            outT[(size_t)d1*KGR + s1*4 + e] = __float2half_rn(acc[mf][nf][3] + bias[n+1]);
        }
    }
}

// ---------------- K2: graph GEMM, split-K(2), M128, 3 stages, 2 CTAs/SM ----------------
__global__ __launch_bounds__(256, 2) void k_graph_h(int dummy)
{
    extern __shared__ char dsm[];
    const int bt = blockIdx.y, t = bt & 1, b = bt >> 1;
    const int ks = blockIdx.z;              // K split half
    const int m0 = blockIdx.x * 128;
    const fp16* A  = g_gh + (size_t)t*MM*KGR + (size_t)b*SLEN*KGR + ks*(KGR/2);
    const fp16* Bg = g_gfullT + ((size_t)t*BV + b)*DD*KGR + ks*(KGR/2);
    float* P = g_gpart + (((size_t)ks*2 + t)*MM + (size_t)b*SLEN)*DD;

    float acc[4][4][4] = {};
    h_core<KGR/2, KGR, KGR, 3, 128, 4>(A, A, A, Bg, m0, 0, acc, dsm);

    const int lane = threadIdx.x & 31, wid = threadIdx.x >> 5;
    const int g = lane >> 2, tig = lane & 3;
    const int wm = wid & 1, wn = wid >> 1;
    #pragma unroll
    for (int mf = 0; mf < 4; mf++) {
        int m = m0 + wm*64 + mf*16 + g;
        #pragma unroll
        for (int nf = 0; nf < 4; nf++) {
            int n = wn*32 + nf*8 + 2*tig;
            float2 v0 = {acc[mf][nf][0], acc[mf][nf][1]};
            float2 v1 = {acc[mf][nf][2], acc[mf][nf][3]};
            *(float2*)(P + (size_t)m*DD + n)     = v0;
            *(float2*)(P + (size_t)(m+8)*DD + n) = v1;
        }
    }
}

// reduce split-K partials -> fp16 gsum
__global__ void k_red() {
    size_t i = ((size_t)blockIdx.x*blockDim.x + threadIdx.x) * 4;  // over 2*MM*DD
    float4 a = *(const float4*)(g_gpart + i);
    float4 b = *(const float4*)(g_gpart + (size_t)2*MM*DD + i);
    fp16 h[4] = {__float2half_rn(a.x+b.x), __float2half_rn(a.y+b.y),
                 __float2half_rn(a.z+b.z), __float2half_rn(a.w+b.w)};
    *(uint2*)(&g_gsumH[0][0] + i) = *(uint2*)h;
}

// ---------------- K3a: r,z = sigmoid([gi,go,X]@[Wr;Wz]^T + b); rgH = fp16(r*X). M64 ----------------
__global__ __launch_bounds__(256, 2) void k_rz_h(const float* __restrict__ Xext, int xsel)
{
    extern __shared__ char dsm[];
    const float* X = state_ptr(Xext, xsel);
    const int m0 = blockIdx.y*64, n0 = blockIdx.x*128;   // n0 in {0,128}
    float acc[4][2][4] = {};
    h_core<384,128,384,2,64,2>(g_gsumH[0], g_gsumH[1], g_stateH, g_WrzH, m0, n0, acc, dsm);

    const int lane = threadIdx.x & 31, wid = threadIdx.x >> 5;
    const int g = lane >> 2, tig = lane & 3;
    #pragma unroll
    for (int mf = 0; mf < 4; mf++) {
        int m = m0 + mf*16 + g;
        #pragma unroll
        for (int nf = 0; nf < 2; nf++) {
            int n = n0 + wid*16 + nf*8 + 2*tig;
            #pragma unroll
            for (int v = 0; v < 4; v++) {
                int mm = (v < 2) ? m : m + 8;
                int nn = n + (v & 1);
                float s = 1.f/(1.f + expf(-(acc[mf][nf][v] + g_brz[nn])));
                if (n0 == 0)
                    g_rgH[(size_t)mm*DD + nn] =
                        __float2half_rn(s * X[(size_t)mm*DD + nn]);
                else
                    g_z[(size_t)mm*DD + (nn - 128)] = s;
            }
        }
    }
}

// ---------------- K3b: h = tanh([gi,go,rg]@Wt^T + bt); out = (1-z)*X + z*h. M64 ----------------
__global__ __launch_bounds__(256, 2) void k_update_h(
    const float* __restrict__ Xext, int xsel,
    const float* __restrict__ bt,
    float* __restrict__ extOut, int osel)
{
    extern __shared__ char dsm[];
    const float* X = state_ptr(Xext, xsel);
    float* out = (osel == 0) ? g_stateA : (osel == 1 ? g_stateB : extOut);
    const int m0 = blockIdx.x*64;
    float acc[4][2][4] = {};
    h_core<384,128,384,2,64,2>(g_gsumH[0], g_gsumH[1], g_rgH, g_WtH, m0, 0, acc, dsm);

    const int lane = threadIdx.x & 31, wid = threadIdx.x >> 5;
    const int g = lane >> 2, tig = lane & 3;
    #pragma unroll
    for (int mf = 0; mf < 4; mf++) {
        int m = m0 + mf*16 + g;
        #pragma unroll
        for (int nf = 0; nf < 2; nf++) {
            int n = wid*16 + nf*8 + 2*tig;
            #pragma unroll
            for (int v = 0; v < 4; v++) {
                int mm = (v < 2) ? m : m + 8;
                int nn = n + (v & 1);
                float h = tanhf(acc[mf][nf][v] + bt[nn]);
                float zv = g_z[(size_t)mm*DD + nn];
                float xv = X[(size_t)mm*DD + nn];
                float o = (1.f - zv)*xv + zv*h;
                out[(size_t)mm*DD + nn] = o;
                g_stateH[(size_t)mm*DD + nn] = __float2half_rn(o);
            }
        }
    }
}

// ---------------- launch ----------------
extern "C" void kernel_launch(void* const* d_in, const int* in_sizes, int n_in,
                              void* d_out, int out_size)
{
    const float* input = (const float*)d_in[0];
    const float* gin   = (const float*)d_in[1];
    const float* gout  = (const float*)d_in[2];
    const float* W_in  = (const float*)d_in[3];
    const float* b_in  = (const float*)d_in[4];
    const float* W_out = (const float*)d_in[5];
    const float* b_out = (const float*)d_in[6];
    const float* W_r   = (const float*)d_in[7];
    const float* b_r   = (const float*)d_in[8];
    const float* W_z   = (const float*)d_in[9];
    const float* b_z   = (const float*)d_in[10];
    const float* W_t   = (const float*)d_in[11];
    const float* b_t   = (const float*)d_in[12];

    cudaFuncSetAttribute(k_graph_h,  cudaFuncAttributeMaxDynamicSharedMemorySize, SM_GR);
    cudaFuncSetAttribute(k_gfull_h,  cudaFuncAttributeMaxDynamicSharedMemorySize, SM_GF);
    cudaFuncSetAttribute(k_rz_h,     cudaFuncAttributeMaxDynamicSharedMemorySize, SM_64);
    cudaFuncSetAttribute(k_update_h, cudaFuncAttributeMaxDynamicSharedMemorySize, SM_64);

    fold_weights<<<dim3(ED, 2), DD>>>(W_in, W_out);
    stack_rzt<<<(256*384 + 255)/256, 256>>>(W_r, W_z, b_r, b_z, W_t);
    k_cvtA<<<dim3((MM/8)*(KGR/256), 2), 256>>>(gin, gout);
    k_cvtX<<<(MM*DD/4 + 255)/256, 256>>>(input);

    int xsel = 2;                       // fp32 state: 2 => external (batchinput)
    for (int s = 0; s < NSTEPS; s++) {
        int osel = (s == NSTEPS-1) ? 2 : (s & 1);
        k_gfull_h <<<dim3(4, 64, 2), 256, SM_GF>>>(b_in, b_out);
        k_graph_h <<<dim3(8, 16, 2), 256, SM_GR>>>(0);
        k_red     <<<(2*MM*DD/4)/256, 256>>>();
        k_rz_h    <<<dim3(2, 128), 256, SM_64>>>(input, xsel);
        k_update_h<<<128, 256, SM_64>>>(input, xsel, b_t, (float*)d_out, osel);
        xsel = osel;
    }
}